// round 3
// baseline (speedup 1.0000x reference)
#include <cuda_runtime.h>

// EfficientAttention3D — GB300 fp32 baseline with f32x2 packed FMA.
// Pipeline:
//   proj_kernel : per 128-col tile: stage x, GEMM Wq/Wk/Wv (8x8 reg tiles, fma.rn.f32x2),
//                 fuse q-softmax(16ch) -> g_qs, exp(keys)+values -> per-tile context
//                 partials + exp-row-sums -> g_part. Keys/values never touch HBM.
//   finalize    : reduce partials over tiles, add CLS contributions, normalize context,
//                 write context_last & CLS_out, build M = Wr @ blockdiag(ctx^T).
//   out_kernel  : attention = M @ qs + br  (single 128x128 GEMM).

#define NB   2
#define CH   128
#define LEN  65536
#define TL   128
#define NT   (LEN/TL)      // 512 tiles per batch
#define NH   8
#define NCLS 4
#define XP   132           // smem pitch (floats) for x / e / v tiles

// scratch (static device globals — no runtime allocation)
__device__ float g_qs[(size_t)NB*CH*LEN];          // softmaxed queries, 64MB
__device__ float g_part[(size_t)NB*NT*2176];       // per-tile: 2048 ctx partials + 128 exp-row-sums
__device__ float g_M[NB*CH*CH];                    // folded Wr @ blockdiag(ctx^T)

typedef unsigned long long ull;

__device__ __forceinline__ ull pk2(float a, float b){ ull r; asm("mov.b64 %0,{%1,%2};":"=l"(r):"f"(a),"f"(b)); return r; }
__device__ __forceinline__ void up2(ull v, float&a, float&b){ asm("mov.b64 {%0,%1},%2;":"=f"(a),"=f"(b):"l"(v)); }
__device__ __forceinline__ void fma2(ull&d, ull a, ull b){ asm("fma.rn.f32x2 %0,%1,%2,%0;":"+l"(d):"l"(a),"l"(b)); }
__device__ __forceinline__ ull add2(ull a, ull b){ ull r; asm("add.rn.f32x2 %0,%1,%2;":"=l"(r):"l"(a),"l"(b)); return r; }
__device__ __forceinline__ ull mul2(ull a, ull b){ ull r; asm("mul.rn.f32x2 %0,%1,%2;":"=l"(r):"l"(a),"l"(b)); return r; }

// C[8 rows x 8 cols] per thread; ws: [128][128] row-major (o,c); xs: [128][XP] (c,l).
// Threads: ty = tid>>4 (row group, 8 rows), tx = tid&15 (col group, 8 cols).
__device__ __forceinline__ void gemm128(const float* __restrict__ ws, const float* __restrict__ xs,
                                        ull acc[8][4], int ty, int tx)
{
#pragma unroll
  for (int i=0;i<8;i++)
#pragma unroll
    for (int j=0;j<4;j++) acc[i][j]=0ull;
  const int xo = tx*8;
#pragma unroll 4
  for (int c=0;c<CH;c+=4){
    float4 w[8];
#pragma unroll
    for (int i=0;i<8;i++) w[i]=*(const float4*)(ws + (ty*8+i)*CH + c);
#pragma unroll
    for (int cc=0;cc<4;cc++){
      const float* xr = xs + (c+cc)*XP + xo;
      ulonglong2 xa = *(const ulonglong2*)xr;        // cols 0..3 as 2x f32x2
      ulonglong2 xb = *(const ulonglong2*)(xr+4);    // cols 4..7
#pragma unroll
      for (int i=0;i<8;i++){
        float wv = cc==0? w[i].x : cc==1? w[i].y : cc==2? w[i].z : w[i].w;
        ull w2 = pk2(wv,wv);
        fma2(acc[i][0], w2, xa.x);
        fma2(acc[i][1], w2, xa.y);
        fma2(acc[i][2], w2, xb.x);
        fma2(acc[i][3], w2, xb.y);
      }
    }
  }
}

__device__ __forceinline__ void loadW(float* ws, const float* __restrict__ W, int tid){
  for (int idx=tid; idx<CH*CH/4; idx+=256)
    ((float4*)ws)[idx] = ((const float4*)W)[idx];
}

__device__ __forceinline__ float dot4(float4 a, float4 b){
  return a.x*b.x + a.y*b.y + a.z*b.z + a.w*b.w;
}

extern "C" __global__ void __launch_bounds__(256,1)
proj_kernel(const float* __restrict__ x,
            const float* __restrict__ Wk, const float* __restrict__ bk,
            const float* __restrict__ Wq, const float* __restrict__ bq,
            const float* __restrict__ Wv, const float* __restrict__ bv)
{
  extern __shared__ float sm[];
  float* xs = sm;               // [128][XP]  x tile, later reused as values tile
  float* ws = xs + CH*XP;       // [128][128] weight buffer
  float* es = ws + CH*CH;       // [128][XP]  exp(keys) tile
  const int tid = threadIdx.x;
  const int ty = tid>>4, tx = tid&15;
  const int n  = blockIdx.y;
  const int tile = blockIdx.x;
  const int l0 = tile*TL;

  // stage x tile (coalesced along l)
  const float* xg = x + (size_t)n*CH*LEN + l0;
  for (int idx=tid; idx<CH*(TL/4); idx+=256){
    int r = idx>>5, c4 = idx&31;
    *(float4*)(xs + r*XP + c4*4) = *(const float4*)(xg + (size_t)r*LEN + c4*4);
  }
  loadW(ws, Wq, tid);
  __syncthreads();

  ull acc[8][4];

  // ---------------- queries: GEMM + softmax over 16 channels (ty pairs via shfl_xor 16)
  gemm128(ws, xs, acc, ty, tx);
  {
    ull cs[4] = {0,0,0,0};
#pragma unroll
    for (int i=0;i<8;i++){
      float b = __ldg(bq + ty*8 + i);
      ull b2 = pk2(b,b);
#pragma unroll
      for (int j=0;j<4;j++){
        float a0,a1; up2(add2(acc[i][j], b2), a0, a1);
        a0 = __expf(a0); a1 = __expf(a1);
        acc[i][j] = pk2(a0,a1);
        cs[j] = add2(cs[j], acc[i][j]);
      }
    }
#pragma unroll
    for (int j=0;j<4;j++){
      ull o = __shfl_xor_sync(0xffffffffu, cs[j], 16);  // partner holds other 8 rows of the head
      cs[j] = add2(cs[j], o);
      float s0,s1; up2(cs[j], s0, s1);
      cs[j] = pk2(1.0f/s0, 1.0f/s1);
    }
    float* qg = g_qs + (size_t)n*CH*LEN + l0 + tx*8;
#pragma unroll
    for (int i=0;i<8;i++){
      float f[8];
#pragma unroll
      for (int j=0;j<4;j++){ ull r = mul2(acc[i][j], cs[j]); up2(r, f[2*j], f[2*j+1]); }
      float* row = qg + (size_t)(ty*8+i)*LEN;
      *(float4*)row     = make_float4(f[0],f[1],f[2],f[3]);
      *(float4*)(row+4) = make_float4(f[4],f[5],f[6],f[7]);
    }
  }

  // ---------------- keys: GEMM -> exp -> es (no max needed: |keys| < ~1.5, |CLS| < ~5)
  __syncthreads();
  loadW(ws, Wk, tid);
  __syncthreads();
  gemm128(ws, xs, acc, ty, tx);
#pragma unroll
  for (int i=0;i<8;i++){
    float b = __ldg(bk + ty*8 + i);
    float f[8];
#pragma unroll
    for (int j=0;j<4;j++){ float a0,a1; up2(acc[i][j],a0,a1); f[2*j]=__expf(a0+b); f[2*j+1]=__expf(a1+b); }
    float* row = es + (ty*8+i)*XP + tx*8;
    *(float4*)row     = make_float4(f[0],f[1],f[2],f[3]);
    *(float4*)(row+4) = make_float4(f[4],f[5],f[6],f[7]);
  }

  // ---------------- values: GEMM -> vs (reuse xs buffer after all reads complete)
  __syncthreads();
  loadW(ws, Wv, tid);
  __syncthreads();
  gemm128(ws, xs, acc, ty, tx);
  __syncthreads();                 // last reads of xs done
  float* vs = xs;
#pragma unroll
  for (int i=0;i<8;i++){
    float b = __ldg(bv + ty*8 + i);
    float f[8];
#pragma unroll
    for (int j=0;j<4;j++){ float a0,a1; up2(acc[i][j],a0,a1); f[2*j]=a0+b; f[2*j+1]=a1+b; }
    float* row = vs + (ty*8+i)*XP + tx*8;
    *(float4*)row     = make_float4(f[0],f[1],f[2],f[3]);
    *(float4*)(row+4) = make_float4(f[4],f[5],f[6],f[7]);
  }
  __syncthreads();

  // ---------------- per-tile context partials (E @ V^T per head) + exp row sums
  {
    const int head = tid>>5, t32 = tid&31;       // warp == head
    const int kg = t32>>2, vg = t32&3;           // 2 k-rows x 4 v-rows per thread
    const int kr0 = head*16 + kg*2;
    const int vr0 = head*16 + vg*4;
    float ca[2][4];
#pragma unroll
    for (int i=0;i<2;i++)
#pragma unroll
      for (int m=0;m<4;m++) ca[i][m]=0.f;
    for (int l=0;l<TL;l+=4){
      float4 e0 = *(const float4*)(es + kr0*XP + l);
      float4 e1 = *(const float4*)(es + (kr0+1)*XP + l);
      float4 v0 = *(const float4*)(vs + vr0*XP + l);
      float4 v1 = *(const float4*)(vs + (vr0+1)*XP + l);
      float4 v2 = *(const float4*)(vs + (vr0+2)*XP + l);
      float4 v3 = *(const float4*)(vs + (vr0+3)*XP + l);
      ca[0][0]+=dot4(e0,v0); ca[0][1]+=dot4(e0,v1); ca[0][2]+=dot4(e0,v2); ca[0][3]+=dot4(e0,v3);
      ca[1][0]+=dot4(e1,v0); ca[1][1]+=dot4(e1,v1); ca[1][2]+=dot4(e1,v2); ca[1][3]+=dot4(e1,v3);
    }
    float* pb = g_part + ((size_t)(n*NT + tile))*2176;
#pragma unroll
    for (int i=0;i<2;i++)
#pragma unroll
      for (int m=0;m<4;m++)
        pb[head*256 + (kg*2+i)*16 + vg*4 + m] = ca[i][m];
    if (tid < CH){
      float s=0.f;
      for (int l=0;l<TL;l+=4){ float4 e=*(const float4*)(es + tid*XP + l); s += e.x+e.y+e.z+e.w; }
      pb[2048 + tid] = s;
    }
  }
}

extern "C" __global__ void finalize_kernel(const float* __restrict__ CLS,
                                           const float* __restrict__ Wr,
                                           float* __restrict__ out)
{
  __shared__ float ctx[2048];
  __shared__ float Ssum[128];
  __shared__ float ecls[512];
  __shared__ float clsv[512];
  __shared__ float cn[2048];
  const int n = blockIdx.x;
  const int tid = threadIdx.x;

  // reduce per-tile partials
  for (int o=tid; o<2176; o+=256){
    float s=0.f;
    const float* p = g_part + (size_t)n*NT*2176 + o;
#pragma unroll 8
    for (int t=0;t<NT;t++) s += p[(size_t)t*2176];
    if (o<2048) ctx[o]=s; else Ssum[o-2048]=s;
  }

  // CLS values + exp (CLS is prepended to keys/queries/values alike)
  // FIX (R2): blockDim is 256 — must stride over all 512 CLS entries.
  for (int i=tid; i<512; i+=256){
    float v = CLS[(size_t)n*CH*NCLS + i];
    clsv[i]=v; ecls[i]=__expf(v);
  }
  __syncthreads();
  if (tid < 128){
    float s = Ssum[tid];
#pragma unroll
    for (int j=0;j<NCLS;j++) s += ecls[tid*NCLS+j];
    Ssum[tid]=s;
  }
  __syncthreads();

  // add CLS contributions and normalize -> cn = softmaxed-keys context
  for (int idx=tid; idx<2048; idx+=256){
    int h=idx>>8, k=(idx>>4)&15, v=idx&15;
    float s=ctx[idx];
#pragma unroll
    for (int j=0;j<NCLS;j++) s += ecls[(h*16+k)*NCLS+j]*clsv[(h*16+v)*NCLS+j];
    cn[idx] = s / Ssum[h*16+k];
  }
  __syncthreads();

  // context_last = context[:, -1]  (16x16, k-major)
  if (tid < 256) out[(size_t)NB*CH*LEN + n*256 + tid] = cn[7*256 + tid];

  // CLS_out[n, v, j] = sum_k cn[7][k][v] * softmax_k(CLS[112+k][j])
  if (tid < 64){
    int v=tid>>2, j=tid&3;
    float se=0.f, a=0.f;
#pragma unroll
    for (int k=0;k<16;k++){
      float e = ecls[(112+k)*NCLS + j];
      se += e;
      a  += cn[7*256 + k*16 + v]*e;
    }
    out[(size_t)NB*CH*LEN + (size_t)NB*256 + n*64 + v*4 + j] = a/se;
  }

  // M[o][h*16+k] = sum_v Wr[o][h*16+v] * cn[h][k][v]
  for (int idx=tid; idx<CH*CH; idx+=256){
    int o=idx>>7, c=idx&127, h=c>>4, k=c&15;
    float m=0.f;
#pragma unroll
    for (int v=0;v<16;v++) m += Wr[o*CH + h*16+v]*cn[h*256 + k*16 + v];
    g_M[(size_t)n*CH*CH + idx] = m;
  }
}

extern "C" __global__ void __launch_bounds__(256,1)
out_kernel(const float* __restrict__ br, float* __restrict__ out)
{
  extern __shared__ float sm[];
  float* ms = sm;               // [128][128]
  float* qs = ms + CH*CH;       // [128][XP]
  const int tid=threadIdx.x, ty=tid>>4, tx=tid&15;
  const int n=blockIdx.y;
  const int l0=blockIdx.x*TL;

  loadW(ms, g_M + (size_t)n*CH*CH, tid);
  const float* qg = g_qs + (size_t)n*CH*LEN + l0;
  for (int idx=tid; idx<CH*(TL/4); idx+=256){
    int r=idx>>5, c4=idx&31;
    *(float4*)(qs + r*XP + c4*4) = *(const float4*)(qg + (size_t)r*LEN + c4*4);
  }
  __syncthreads();

  ull acc[8][4];
  gemm128(ms, qs, acc, ty, tx);

  float* og = out + (size_t)n*CH*LEN + l0 + tx*8;
#pragma unroll
  for (int i=0;i<8;i++){
    float b = __ldg(br + ty*8+i);
    float f[8];
#pragma unroll
    for (int j=0;j<4;j++){ float a0,a1; up2(acc[i][j],a0,a1); f[2*j]=a0+b; f[2*j+1]=a1+b; }
    float* row = og + (size_t)(ty*8+i)*LEN;
    *(float4*)row     = make_float4(f[0],f[1],f[2],f[3]);
    *(float4*)(row+4) = make_float4(f[4],f[5],f[6],f[7]);
  }
}

extern "C" void kernel_launch(void* const* d_in, const int* in_sizes, int n_in,
                              void* d_out, int out_size)
{
  const float* x  = (const float*)d_in[0];
  const float* CLS= (const float*)d_in[1];
  const float* Wk = (const float*)d_in[2];
  const float* bk = (const float*)d_in[3];
  const float* Wq = (const float*)d_in[4];
  const float* bq = (const float*)d_in[5];
  const float* Wv = (const float*)d_in[6];
  const float* bv = (const float*)d_in[7];
  const float* Wr = (const float*)d_in[8];
  const float* br = (const float*)d_in[9];
  float* out = (float*)d_out;

  const int smem_proj = (CH*XP + CH*CH + CH*XP)*(int)sizeof(float);  // 200704 B
  const int smem_out  = (CH*CH + CH*XP)*(int)sizeof(float);          // 133120 B
  cudaFuncSetAttribute(proj_kernel, cudaFuncAttributeMaxDynamicSharedMemorySize, smem_proj);
  cudaFuncSetAttribute(out_kernel,  cudaFuncAttributeMaxDynamicSharedMemorySize, smem_out);

  dim3 grid(NT, NB);
  proj_kernel<<<grid, 256, smem_proj>>>(x, Wk, bk, Wq, bq, Wv, bv);
  finalize_kernel<<<NB, 256>>>(CLS, Wr, out);
  out_kernel<<<grid, 256, smem_out>>>(br, out);
}

// round 5
// speedup vs baseline: 1.3281x; 1.3281x over previous
#include <cuda_runtime.h>
#include <cstdint>

// EfficientAttention3D — mma.sync tf32 version (sm_103 plain target; no tcgen05).
//   proj_kernel : per 128-col tile: stage x (tf32) + W (tf32), m16n8k8 tf32 MMA for
//                 Q/K/V; epilogues on register fragments: q-softmax -> g_qs,
//                 exp(keys) -> es, values -> vs, then per-head context MMA
//                 E@V^T -> g_part (+ exp row sums). Keys/values never hit HBM.
//   finalize    : reduce partials, add CLS, normalize, context_last & CLS_out,
//                 M = Wr @ blockdiag(ctx^T).
//   out_kernel  : attention = M @ qs + br via one tf32 MMA per tile.

#define NB   2
#define CH   128
#define LEN  65536
#define TL   128
#define NT   (LEN/TL)
#define NCLS 4
#define PIT  132      // smem pitch in floats

// proj smem layout (floats)
#define S_XS 0
#define S_WS (CH*PIT)          // 16896
#define S_ES (2*CH*PIT)        // 33792 (exp keys)
#define S_RS (3*CH*PIT)        // 50688 (256 rowsum partials)
#define SMEM_PROJ ((3*CH*PIT + 256)*4)   // 203776 B
#define SMEM_OUT  ((2*CH*PIT)*4)         // 135168 B

__device__ float g_qs[(size_t)NB*CH*LEN];
__device__ float g_part[(size_t)NB*NT*2176];
__device__ float g_M[NB*CH*CH];

__device__ __forceinline__ float tf32r(float f){
  uint32_t u; asm("cvt.rna.tf32.f32 %0, %1;":"=r"(u):"f"(f)); return __uint_as_float(u);
}
__device__ __forceinline__ void mma8(float d[4], const uint32_t a[4], const uint32_t b[2]){
  asm volatile("mma.sync.aligned.m16n8k8.row.col.f32.tf32.tf32.f32 "
    "{%0,%1,%2,%3}, {%4,%5,%6,%7}, {%8,%9}, {%0,%1,%2,%3};"
    : "+f"(d[0]),"+f"(d[1]),"+f"(d[2]),"+f"(d[3])
    : "r"(a[0]),"r"(a[1]),"r"(a[2]),"r"(a[3]),"r"(b[0]),"r"(b[1]));
}

// stage row-major 128x128 matrix into smem pitch-PIT with tf32 rounding
__device__ __forceinline__ void stageM(float* dst, const float* __restrict__ src, int tid, int srcPitch){
  for (int idx=tid; idx<4096; idx+=256){
    int o=idx>>5, c4=(idx&31)*4;
    float4 w = *(const float4*)(src + (size_t)o*srcPitch + c4);
    w.x=tf32r(w.x); w.y=tf32r(w.y); w.z=tf32r(w.z); w.w=tf32r(w.w);
    *(float4*)(dst + o*PIT + c4) = w;
  }
}

// A = ws[128 rows(ch-out) x 128 k], B = xs[128 k x 128 n]; acc[2][8][4]
// warp: wr=wid&3 (rows 32*wr..+31), wc=wid>>2 (cols 64*wc..+63)
__device__ __forceinline__ void gemm(const float* __restrict__ ws, const float* __restrict__ xs,
                                     float acc[2][8][4], int wr, int wc, int lane)
{
#pragma unroll
  for (int m=0;m<2;m++)
#pragma unroll
    for (int n=0;n<8;n++)
#pragma unroll
      for (int j=0;j<4;j++) acc[m][n][j]=0.f;
  const int lr = lane>>2, lc = lane&3;
#pragma unroll 4
  for (int k=0;k<16;k++){
    const int koff = k*8;
    uint32_t a[2][4];
#pragma unroll
    for (int m=0;m<2;m++){
      const float* ap = ws + (wr*32 + m*16 + lr)*PIT + koff + lc;
      a[m][0]=__float_as_uint(ap[0]);
      a[m][1]=__float_as_uint(ap[8*PIT]);
      a[m][2]=__float_as_uint(ap[4]);
      a[m][3]=__float_as_uint(ap[8*PIT+4]);
    }
#pragma unroll
    for (int n=0;n<8;n++){
      uint32_t b[2];
      const float* bp = xs + (koff + lc)*PIT + wc*64 + n*8 + lr;
      b[0]=__float_as_uint(bp[0]);
      b[1]=__float_as_uint(bp[4*PIT]);
      mma8(acc[0][n], a[0], b);
      mma8(acc[1][n], a[1], b);
    }
  }
}

extern "C" __global__ void __launch_bounds__(256,1)
proj_kernel(const float* __restrict__ x,
            const float* __restrict__ Wk, const float* __restrict__ bk,
            const float* __restrict__ Wq, const float* __restrict__ bq,
            const float* __restrict__ Wv, const float* __restrict__ bv)
{
  extern __shared__ float sm[];
  float* xs = sm + S_XS;
  float* ws = sm + S_WS;   // weights, later reused as vs
  float* es = sm + S_ES;
  float* rs = sm + S_RS;
  const int tid = threadIdx.x, wid = tid>>5, lane = tid&31;
  const int wr = wid&3, wc = wid>>2, lr = lane>>2, lc = lane&3;
  const int n = blockIdx.y, l0 = blockIdx.x*TL;

  stageM(xs, x + (size_t)n*CH*LEN + l0, tid, LEN);
  stageM(ws, Wq, tid, CH);
  __syncthreads();

  float acc[2][8][4];

  // ---------------- Q: GEMM + softmax over the 16 channels of each head ----------------
  gemm(ws, xs, acc, wr, wc, lane);
  {
    float* qg = g_qs + (size_t)n*CH*LEN + l0;
#pragma unroll
    for (int m=0;m<2;m++){
      const int rt = wr*32 + m*16 + lr, rb = rt + 8;
      const float bt = __ldg(bq + rt), bb = __ldg(bq + rb);
      float e[8][4];
      float s0[8], s1[8];
#pragma unroll
      for (int nn=0;nn<8;nn++){
        e[nn][0]=__expf(acc[m][nn][0]+bt); e[nn][1]=__expf(acc[m][nn][1]+bt);
        e[nn][2]=__expf(acc[m][nn][2]+bb); e[nn][3]=__expf(acc[m][nn][3]+bb);
        s0[nn]=e[nn][0]+e[nn][2]; s1[nn]=e[nn][1]+e[nn][3];
      }
#pragma unroll
      for (int nn=0;nn<8;nn++){
        s0[nn] += __shfl_xor_sync(0xffffffffu, s0[nn], 4);
        s0[nn] += __shfl_xor_sync(0xffffffffu, s0[nn], 8);
        s0[nn] += __shfl_xor_sync(0xffffffffu, s0[nn], 16);
        s1[nn] += __shfl_xor_sync(0xffffffffu, s1[nn], 4);
        s1[nn] += __shfl_xor_sync(0xffffffffu, s1[nn], 8);
        s1[nn] += __shfl_xor_sync(0xffffffffu, s1[nn], 16);
        float i0 = __frcp_rn(s0[nn]), i1 = __frcp_rn(s1[nn]);
        int c = wc*64 + nn*8 + lc*2;
        *(float2*)(qg + (size_t)rt*LEN + c) = make_float2(e[nn][0]*i0, e[nn][1]*i1);
        *(float2*)(qg + (size_t)rb*LEN + c) = make_float2(e[nn][2]*i0, e[nn][3]*i1);
      }
    }
  }

  // ---------------- K: GEMM -> exp -> es (+ rowsum partials) ----------------
  __syncthreads();
  stageM(ws, Wk, tid, CH);
  __syncthreads();
  gemm(ws, xs, acc, wr, wc, lane);
#pragma unroll
  for (int m=0;m<2;m++){
    const int rt = wr*32 + m*16 + lr, rb = rt + 8;
    const float bt = __ldg(bk + rt), bb = __ldg(bk + rb);
    float rowt=0.f, rowb=0.f;
#pragma unroll
    for (int nn=0;nn<8;nn++){
      float e0=__expf(acc[m][nn][0]+bt), e1=__expf(acc[m][nn][1]+bt);
      float e2=__expf(acc[m][nn][2]+bb), e3=__expf(acc[m][nn][3]+bb);
      rowt += e0+e1; rowb += e2+e3;
      int c = wc*64 + nn*8 + lc*2;
      *(float2*)(es + rt*PIT + c) = make_float2(tf32r(e0), tf32r(e1));
      *(float2*)(es + rb*PIT + c) = make_float2(tf32r(e2), tf32r(e3));
    }
    rowt += __shfl_xor_sync(0xffffffffu, rowt, 1);
    rowt += __shfl_xor_sync(0xffffffffu, rowt, 2);
    rowb += __shfl_xor_sync(0xffffffffu, rowb, 1);
    rowb += __shfl_xor_sync(0xffffffffu, rowb, 2);
    if (lc == 0){ rs[rt*2+wc]=rowt; rs[rb*2+wc]=rowb; }
  }

  // ---------------- V: GEMM -> vs (reuse ws after sync) ----------------
  __syncthreads();
  stageM(ws, Wv, tid, CH);
  __syncthreads();
  gemm(ws, xs, acc, wr, wc, lane);
  __syncthreads();               // everyone done reading ws
  float* vs = ws;
#pragma unroll
  for (int m=0;m<2;m++){
    const int rt = wr*32 + m*16 + lr, rb = rt + 8;
    const float bt = __ldg(bv + rt), bb = __ldg(bv + rb);
#pragma unroll
    for (int nn=0;nn<8;nn++){
      int c = wc*64 + nn*8 + lc*2;
      *(float2*)(vs + rt*PIT + c) = make_float2(tf32r(acc[m][nn][0]+bt), tf32r(acc[m][nn][1]+bt));
      *(float2*)(vs + rb*PIT + c) = make_float2(tf32r(acc[m][nn][2]+bb), tf32r(acc[m][nn][3]+bb));
    }
  }
  __syncthreads();

  // ---------------- per-head context MMA: ctx[h] = E_h @ V_h^T  (16x16, K=128) ----------------
  float* pb = g_part + ((size_t)(n*NT + blockIdx.x))*2176;
  {
    const int h = wid;  // warp == head
    const float* ea = es + h*16*PIT;
    const float* va = vs + h*16*PIT;
    float ca[2][4];
#pragma unroll
    for (int nt=0;nt<2;nt++)
#pragma unroll
      for (int j=0;j<4;j++) ca[nt][j]=0.f;
#pragma unroll 4
    for (int k=0;k<16;k++){
      const int koff=k*8;
      uint32_t a[4];
      const float* ap = ea + lr*PIT + koff + lc;
      a[0]=__float_as_uint(ap[0]); a[1]=__float_as_uint(ap[8*PIT]);
      a[2]=__float_as_uint(ap[4]); a[3]=__float_as_uint(ap[8*PIT+4]);
#pragma unroll
      for (int nt=0;nt<2;nt++){
        uint32_t b[2];
        const float* bp = va + (nt*8+lr)*PIT + koff + lc;
        b[0]=__float_as_uint(bp[0]); b[1]=__float_as_uint(bp[4]);
        mma8(ca[nt], a, b);
      }
    }
#pragma unroll
    for (int nt=0;nt<2;nt++){
      int v = nt*8 + lc*2;
      *(float2*)(pb + h*256 + lr*16     + v) = make_float2(ca[nt][0], ca[nt][1]);
      *(float2*)(pb + h*256 + (lr+8)*16 + v) = make_float2(ca[nt][2], ca[nt][3]);
    }
  }
  if (tid < CH) pb[2048 + tid] = rs[tid*2] + rs[tid*2+1];
}

// ---------------- finalize (unchanged from R3, passing) ----------------
extern "C" __global__ void finalize_kernel(const float* __restrict__ CLS,
                                           const float* __restrict__ Wr,
                                           float* __restrict__ out)
{
  __shared__ float ctx[2048];
  __shared__ float Ssum[128];
  __shared__ float ecls[512];
  __shared__ float clsv[512];
  __shared__ float cn[2048];
  const int n = blockIdx.x;
  const int tid = threadIdx.x;

  for (int o=tid; o<2176; o+=256){
    float s=0.f;
    const float* p = g_part + (size_t)n*NT*2176 + o;
#pragma unroll 8
    for (int t=0;t<NT;t++) s += p[(size_t)t*2176];
    if (o<2048) ctx[o]=s; else Ssum[o-2048]=s;
  }
  for (int i=tid; i<512; i+=256){
    float v = CLS[(size_t)n*CH*NCLS + i];
    clsv[i]=v; ecls[i]=__expf(v);
  }
  __syncthreads();
  if (tid < 128){
    float s = Ssum[tid];
#pragma unroll
    for (int j=0;j<NCLS;j++) s += ecls[tid*NCLS+j];
    Ssum[tid]=s;
  }
  __syncthreads();
  for (int idx=tid; idx<2048; idx+=256){
    int h=idx>>8, k=(idx>>4)&15, v=idx&15;
    float s=ctx[idx];
#pragma unroll
    for (int j=0;j<NCLS;j++) s += ecls[(h*16+k)*NCLS+j]*clsv[(h*16+v)*NCLS+j];
    cn[idx] = s / Ssum[h*16+k];
  }
  __syncthreads();
  if (tid < 256) out[(size_t)NB*CH*LEN + n*256 + tid] = cn[7*256 + tid];
  if (tid < 64){
    int v=tid>>2, j=tid&3;
    float se=0.f, a=0.f;
#pragma unroll
    for (int k=0;k<16;k++){
      float e = ecls[(112+k)*NCLS + j];
      se += e;
      a  += cn[7*256 + k*16 + v]*e;
    }
    out[(size_t)NB*CH*LEN + (size_t)NB*256 + n*64 + v*4 + j] = a/se;
  }
  for (int idx=tid; idx<CH*CH; idx+=256){
    int o=idx>>7, c=idx&127, h=c>>4, k=c&15;
    float m=0.f;
#pragma unroll
    for (int v=0;v<16;v++) m += Wr[o*CH + h*16+v]*cn[h*256 + k*16 + v];
    g_M[(size_t)n*CH*CH + idx] = m;
  }
}

// ---------------- out: attention = M @ qs + br ----------------
extern "C" __global__ void __launch_bounds__(256,1)
out_kernel(const float* __restrict__ br, float* __restrict__ out)
{
  extern __shared__ float sm[];
  float* xs = sm;              // qs tile
  float* ms = sm + CH*PIT;     // M
  const int tid = threadIdx.x, wid = tid>>5, lane = tid&31;
  const int wr = wid&3, wc = wid>>2, lr = lane>>2, lc = lane&3;
  const int n = blockIdx.y, l0 = blockIdx.x*TL;

  stageM(xs, g_qs + (size_t)n*CH*LEN + l0, tid, LEN);
  stageM(ms, g_M + (size_t)n*CH*CH, tid, CH);
  __syncthreads();

  float acc[2][8][4];
  gemm(ms, xs, acc, wr, wc, lane);

  float* og = out + (size_t)n*CH*LEN + l0;
#pragma unroll
  for (int m=0;m<2;m++){
    const int rt = wr*32 + m*16 + lr, rb = rt + 8;
    const float bt = __ldg(br + rt), bb = __ldg(br + rb);
#pragma unroll
    for (int nn=0;nn<8;nn++){
      int c = wc*64 + nn*8 + lc*2;
      *(float2*)(og + (size_t)rt*LEN + c) = make_float2(acc[m][nn][0]+bt, acc[m][nn][1]+bt);
      *(float2*)(og + (size_t)rb*LEN + c) = make_float2(acc[m][nn][2]+bb, acc[m][nn][3]+bb);
    }
  }
}

extern "C" void kernel_launch(void* const* d_in, const int* in_sizes, int n_in,
                              void* d_out, int out_size)
{
  const float* x  = (const float*)d_in[0];
  const float* CLS= (const float*)d_in[1];
  const float* Wk = (const float*)d_in[2];
  const float* bk = (const float*)d_in[3];
  const float* Wq = (const float*)d_in[4];
  const float* bq = (const float*)d_in[5];
  const float* Wv = (const float*)d_in[6];
  const float* bv = (const float*)d_in[7];
  const float* Wr = (const float*)d_in[8];
  const float* br = (const float*)d_in[9];
  float* out = (float*)d_out;

  cudaFuncSetAttribute(proj_kernel, cudaFuncAttributeMaxDynamicSharedMemorySize, SMEM_PROJ);
  cudaFuncSetAttribute(out_kernel,  cudaFuncAttributeMaxDynamicSharedMemorySize, SMEM_OUT);

  dim3 grid(NT, NB);
  proj_kernel<<<grid, 256, SMEM_PROJ>>>(x, Wk, bk, Wq, bq, Wv, bv);
  finalize_kernel<<<NB, 256>>>(CLS, Wr, out);
  out_kernel<<<grid, 256, SMEM_OUT>>>(br, out);
}

// round 7
// speedup vs baseline: 2.4052x; 1.8111x over previous
#include <cuda_runtime.h>
#include <cstdint>

// EfficientAttention3D — mma.sync tf32, 512-thread CTAs (R6).
//   proj_kernel : 16 warps, warp tile 32x32. Q/K/V tf32 MMAs; q-softmax -> g_qs,
//                 exp(K) -> es, V -> vs, per-head context MMA (2 warps/head,
//                 split-K) -> g_part[elem][tile] (+ rowsums). K/V never hit HBM.
//   finalize    : coalesced warp-per-element tile reduction, CLS terms, normalize,
//                 context_last & CLS_out, M = Wr @ blockdiag(ctx^T).
//   out_kernel  : attention = M @ qs + br, one tf32 MMA per tile, 16 warps.

#define NB   2
#define CH   128
#define LEN  65536
#define TL   128
#define NT   (LEN/TL)
#define NCLS 4
#define PIT  132

#define S_XS 0
#define S_WS (CH*PIT)
#define S_ES (2*CH*PIT)
#define S_RS (3*CH*PIT)                  // 512 floats rowsum partials (4 col groups)
#define SMEM_PROJ ((3*CH*PIT + 512)*4)   // 204800 B
#define SMEM_OUT  ((2*CH*PIT)*4)         // 135168 B

__device__ float g_qs[(size_t)NB*CH*LEN];
__device__ float g_part[(size_t)NB*2176*NT];   // [n][elem][tile]
__device__ float g_M[NB*CH*CH];

__device__ __forceinline__ float tf32r(float f){
  uint32_t u; asm("cvt.rna.tf32.f32 %0, %1;":"=r"(u):"f"(f)); return __uint_as_float(u);
}
__device__ __forceinline__ void mma8(float d[4], const uint32_t a[4], const uint32_t b[2]){
  asm volatile("mma.sync.aligned.m16n8k8.row.col.f32.tf32.tf32.f32 "
    "{%0,%1,%2,%3}, {%4,%5,%6,%7}, {%8,%9}, {%0,%1,%2,%3};"
    : "+f"(d[0]),"+f"(d[1]),"+f"(d[2]),"+f"(d[3])
    : "r"(a[0]),"r"(a[1]),"r"(a[2]),"r"(a[3]),"r"(b[0]),"r"(b[1]));
}

// stage row-major 128x128 into pitch-PIT smem, tf32-rounded (512 threads)
__device__ __forceinline__ void stageM(float* dst, const float* __restrict__ src, int tid, int srcPitch){
  for (int idx=tid; idx<4096; idx+=512){
    int o=idx>>5, c4=(idx&31)*4;
    float4 w = *(const float4*)(src + (size_t)o*srcPitch + c4);
    w.x=tf32r(w.x); w.y=tf32r(w.y); w.z=tf32r(w.z); w.w=tf32r(w.w);
    *(float4*)(dst + o*PIT + c4) = w;
  }
}

// warp tile 32 rows x 32 cols: wr=wid&3 rows 32*wr.., wc=wid>>2 cols 32*wc..
__device__ __forceinline__ void gemm(const float* __restrict__ ws, const float* __restrict__ xs,
                                     float acc[2][4][4], int wr, int wc, int lane)
{
#pragma unroll
  for (int m=0;m<2;m++)
#pragma unroll
    for (int n=0;n<4;n++)
#pragma unroll
      for (int j=0;j<4;j++) acc[m][n][j]=0.f;
  const int lr = lane>>2, lc = lane&3;
#pragma unroll 4
  for (int k=0;k<16;k++){
    const int koff = k*8;
    uint32_t a[2][4];
#pragma unroll
    for (int m=0;m<2;m++){
      const float* ap = ws + (wr*32 + m*16 + lr)*PIT + koff + lc;
      a[m][0]=__float_as_uint(ap[0]);
      a[m][1]=__float_as_uint(ap[8*PIT]);
      a[m][2]=__float_as_uint(ap[4]);
      a[m][3]=__float_as_uint(ap[8*PIT+4]);
    }
#pragma unroll
    for (int n=0;n<4;n++){
      uint32_t b[2];
      const float* bp = xs + (koff + lc)*PIT + wc*32 + n*8 + lr;
      b[0]=__float_as_uint(bp[0]);
      b[1]=__float_as_uint(bp[4*PIT]);
      mma8(acc[0][n], a[0], b);
      mma8(acc[1][n], a[1], b);
    }
  }
}

extern "C" __global__ void __launch_bounds__(512,1)
proj_kernel(const float* __restrict__ x,
            const float* __restrict__ Wk, const float* __restrict__ bk,
            const float* __restrict__ Wq, const float* __restrict__ bq,
            const float* __restrict__ Wv, const float* __restrict__ bv)
{
  extern __shared__ float sm[];
  float* xs = sm + S_XS;
  float* ws = sm + S_WS;   // weights, later vs
  float* es = sm + S_ES;
  float* rs = sm + S_RS;
  const int tid = threadIdx.x, wid = tid>>5, lane = tid&31;
  const int wr = wid&3, wc = wid>>2, lr = lane>>2, lc = lane&3;
  const int n = blockIdx.y, l0 = blockIdx.x*TL;

  stageM(xs, x + (size_t)n*CH*LEN + l0, tid, LEN);
  stageM(ws, Wq, tid, CH);
  __syncthreads();

  float acc[2][4][4];

  // ---- Q: GEMM + 16-channel softmax ----
  gemm(ws, xs, acc, wr, wc, lane);
  {
    float* qg = g_qs + (size_t)n*CH*LEN + l0;
#pragma unroll
    for (int m=0;m<2;m++){
      const int rt = wr*32 + m*16 + lr, rb = rt + 8;
      const float bt = __ldg(bq + rt), bb = __ldg(bq + rb);
      float e[4][4], s0[4], s1[4];
#pragma unroll
      for (int nn=0;nn<4;nn++){
        e[nn][0]=__expf(acc[m][nn][0]+bt); e[nn][1]=__expf(acc[m][nn][1]+bt);
        e[nn][2]=__expf(acc[m][nn][2]+bb); e[nn][3]=__expf(acc[m][nn][3]+bb);
        s0[nn]=e[nn][0]+e[nn][2]; s1[nn]=e[nn][1]+e[nn][3];
      }
#pragma unroll
      for (int nn=0;nn<4;nn++){
        s0[nn] += __shfl_xor_sync(0xffffffffu, s0[nn], 4);
        s0[nn] += __shfl_xor_sync(0xffffffffu, s0[nn], 8);
        s0[nn] += __shfl_xor_sync(0xffffffffu, s0[nn], 16);
        s1[nn] += __shfl_xor_sync(0xffffffffu, s1[nn], 4);
        s1[nn] += __shfl_xor_sync(0xffffffffu, s1[nn], 8);
        s1[nn] += __shfl_xor_sync(0xffffffffu, s1[nn], 16);
        float i0 = __frcp_rn(s0[nn]), i1 = __frcp_rn(s1[nn]);
        int c = wc*32 + nn*8 + lc*2;
        *(float2*)(qg + (size_t)rt*LEN + c) = make_float2(e[nn][0]*i0, e[nn][1]*i1);
        *(float2*)(qg + (size_t)rb*LEN + c) = make_float2(e[nn][2]*i0, e[nn][3]*i1);
      }
    }
  }

  // ---- K: GEMM -> exp -> es (+ rowsum partials per col-group) ----
  __syncthreads();
  stageM(ws, Wk, tid, CH);
  __syncthreads();
  gemm(ws, xs, acc, wr, wc, lane);
#pragma unroll
  for (int m=0;m<2;m++){
    const int rt = wr*32 + m*16 + lr, rb = rt + 8;
    const float bt = __ldg(bk + rt), bb = __ldg(bk + rb);
    float rowt=0.f, rowb=0.f;
#pragma unroll
    for (int nn=0;nn<4;nn++){
      float e0=__expf(acc[m][nn][0]+bt), e1=__expf(acc[m][nn][1]+bt);
      float e2=__expf(acc[m][nn][2]+bb), e3=__expf(acc[m][nn][3]+bb);
      rowt += e0+e1; rowb += e2+e3;
      int c = wc*32 + nn*8 + lc*2;
      *(float2*)(es + rt*PIT + c) = make_float2(tf32r(e0), tf32r(e1));
      *(float2*)(es + rb*PIT + c) = make_float2(tf32r(e2), tf32r(e3));
    }
    rowt += __shfl_xor_sync(0xffffffffu, rowt, 1);
    rowt += __shfl_xor_sync(0xffffffffu, rowt, 2);
    rowb += __shfl_xor_sync(0xffffffffu, rowb, 1);
    rowb += __shfl_xor_sync(0xffffffffu, rowb, 2);
    if (lc == 0){ rs[rt*4+wc]=rowt; rs[rb*4+wc]=rowb; }
  }

  // ---- V: GEMM -> vs ----
  __syncthreads();
  stageM(ws, Wv, tid, CH);
  __syncthreads();
  gemm(ws, xs, acc, wr, wc, lane);
  __syncthreads();
  float* vs = ws;
#pragma unroll
  for (int m=0;m<2;m++){
    const int rt = wr*32 + m*16 + lr, rb = rt + 8;
    const float bt = __ldg(bv + rt), bb = __ldg(bv + rb);
#pragma unroll
    for (int nn=0;nn<4;nn++){
      int c = wc*32 + nn*8 + lc*2;
      *(float2*)(vs + rt*PIT + c) = make_float2(tf32r(acc[m][nn][0]+bt), tf32r(acc[m][nn][1]+bt));
      *(float2*)(vs + rb*PIT + c) = make_float2(tf32r(acc[m][nn][2]+bb), tf32r(acc[m][nn][3]+bb));
    }
  }
  __syncthreads();

  // ---- context: ctx[h] = E_h @ V_h^T (16x16, K=128 split over 2 warps) ----
  float* pb = g_part + (size_t)n*2176*NT + blockIdx.x;   // [elem][tile], this tile's column
  float* cbuf = xs;   // xs free now
  {
    const int h = wid>>1, kh = wid&1;
    const float* ea = es + h*16*PIT;
    const float* va = vs + h*16*PIT;
    float ca[2][4];
#pragma unroll
    for (int nt=0;nt<2;nt++)
#pragma unroll
      for (int j=0;j<4;j++) ca[nt][j]=0.f;
#pragma unroll 4
    for (int k=0;k<8;k++){
      const int koff = kh*64 + k*8;
      uint32_t a[4];
      const float* ap = ea + lr*PIT + koff + lc;
      a[0]=__float_as_uint(ap[0]); a[1]=__float_as_uint(ap[8*PIT]);
      a[2]=__float_as_uint(ap[4]); a[3]=__float_as_uint(ap[8*PIT+4]);
#pragma unroll
      for (int nt=0;nt<2;nt++){
        uint32_t b[2];
        const float* bp = va + (nt*8+lr)*PIT + koff + lc;
        b[0]=__float_as_uint(bp[0]); b[1]=__float_as_uint(bp[4]);
        mma8(ca[nt], a, b);
      }
    }
    if (kh == 1){
#pragma unroll
      for (int nt=0;nt<2;nt++){
        int v = nt*8 + lc*2;
        *(float2*)(cbuf + h*256 + lr*16     + v) = make_float2(ca[nt][0], ca[nt][1]);
        *(float2*)(cbuf + h*256 + (lr+8)*16 + v) = make_float2(ca[nt][2], ca[nt][3]);
      }
    }
    __syncthreads();
    if (kh == 0){
#pragma unroll
      for (int nt=0;nt<2;nt++){
        int v = nt*8 + lc*2;
        pb[(size_t)(h*256 + lr*16 + v    )*NT] = ca[nt][0] + cbuf[h*256 + lr*16 + v];
        pb[(size_t)(h*256 + lr*16 + v + 1)*NT] = ca[nt][1] + cbuf[h*256 + lr*16 + v + 1];
        pb[(size_t)(h*256 + (lr+8)*16 + v    )*NT] = ca[nt][2] + cbuf[h*256 + (lr+8)*16 + v];
        pb[(size_t)(h*256 + (lr+8)*16 + v + 1)*NT] = ca[nt][3] + cbuf[h*256 + (lr+8)*16 + v + 1];
      }
    }
  }
  if (tid < CH)
    pb[(size_t)(2048 + tid)*NT] = rs[tid*4] + rs[tid*4+1] + rs[tid*4+2] + rs[tid*4+3];
}

// ---------------- finalize ----------------
extern "C" __global__ void __launch_bounds__(512,1)
finalize_kernel(const float* __restrict__ CLS,
                const float* __restrict__ Wr,
                float* __restrict__ out)
{
  __shared__ float ctx[2048];
  __shared__ float Ssum[128];
  __shared__ float ecls[512];
  __shared__ float clsv[512];
  __shared__ float cn[2048];
  const int n = blockIdx.x;
  const int tid = threadIdx.x, wid = tid>>5, lane = tid&31;

  // coalesced warp-per-element reduction over NT tiles
  for (int o = wid; o < 2176; o += 16){
    const float* p = g_part + ((size_t)n*2176 + o)*NT + lane*4;
    float s = 0.f;
#pragma unroll
    for (int i=0;i<4;i++){ float4 v = *(const float4*)(p + i*128); s += v.x+v.y+v.z+v.w; }
    s += __shfl_xor_sync(0xffffffffu, s, 16);
    s += __shfl_xor_sync(0xffffffffu, s, 8);
    s += __shfl_xor_sync(0xffffffffu, s, 4);
    s += __shfl_xor_sync(0xffffffffu, s, 2);
    s += __shfl_xor_sync(0xffffffffu, s, 1);
    if (lane == 0){ if (o < 2048) ctx[o] = s; else Ssum[o-2048] = s; }
  }
  if (tid < 512){
    float v = CLS[(size_t)n*CH*NCLS + tid];
    clsv[tid]=v; ecls[tid]=__expf(v);
  }
  __syncthreads();
  if (tid < 128){
    float s = Ssum[tid];
#pragma unroll
    for (int j=0;j<NCLS;j++) s += ecls[tid*NCLS+j];
    Ssum[tid]=s;
  }
  __syncthreads();
  for (int idx=tid; idx<2048; idx+=512){
    int h=idx>>8, k=(idx>>4)&15, v=idx&15;
    float s=ctx[idx];
#pragma unroll
    for (int j=0;j<NCLS;j++) s += ecls[(h*16+k)*NCLS+j]*clsv[(h*16+v)*NCLS+j];
    cn[idx] = s / Ssum[h*16+k];
  }
  __syncthreads();
  if (tid < 256) out[(size_t)NB*CH*LEN + n*256 + tid] = cn[7*256 + tid];
  if (tid < 64){
    int v=tid>>2, j=tid&3;
    float se=0.f, a=0.f;
#pragma unroll
    for (int k=0;k<16;k++){
      float e = ecls[(112+k)*NCLS + j];
      se += e;
      a  += cn[7*256 + k*16 + v]*e;
    }
    out[(size_t)NB*CH*LEN + (size_t)NB*256 + n*64 + v*4 + j] = a/se;
  }
  for (int idx=tid; idx<CH*CH; idx+=512){
    int o=idx>>7, c=idx&127, h=c>>4, k=c&15;
    float m=0.f;
#pragma unroll
    for (int v=0;v<16;v++) m += Wr[o*CH + h*16+v]*cn[h*256 + k*16 + v];
    g_M[(size_t)n*CH*CH + idx] = m;
  }
}

// ---------------- out: attention = M @ qs + br ----------------
extern "C" __global__ void __launch_bounds__(512,1)
out_kernel(const float* __restrict__ br, float* __restrict__ out)
{
  extern __shared__ float sm[];
  float* xs = sm;
  float* ms = sm + CH*PIT;
  const int tid = threadIdx.x, wid = tid>>5, lane = tid&31;
  const int wr = wid&3, wc = wid>>2, lr = lane>>2, lc = lane&3;
  const int n = blockIdx.y, l0 = blockIdx.x*TL;

  stageM(xs, g_qs + (size_t)n*CH*LEN + l0, tid, LEN);
  stageM(ms, g_M + (size_t)n*CH*CH, tid, CH);
  __syncthreads();

  float acc[2][4][4];
  gemm(ms, xs, acc, wr, wc, lane);

  float* og = out + (size_t)n*CH*LEN + l0;
#pragma unroll
  for (int m=0;m<2;m++){
    const int rt = wr*32 + m*16 + lr, rb = rt + 8;
    const float bt = __ldg(br + rt), bb = __ldg(br + rb);
#pragma unroll
    for (int nn=0;nn<4;nn++){
      int c = wc*32 + nn*8 + lc*2;
      *(float2*)(og + (size_t)rt*LEN + c) = make_float2(acc[m][nn][0]+bt, acc[m][nn][1]+bt);
      *(float2*)(og + (size_t)rb*LEN + c) = make_float2(acc[m][nn][2]+bb, acc[m][nn][3]+bb);
    }
  }
}

extern "C" void kernel_launch(void* const* d_in, const int* in_sizes, int n_in,
                              void* d_out, int out_size)
{
  const float* x  = (const float*)d_in[0];
  const float* CLS= (const float*)d_in[1];
  const float* Wk = (const float*)d_in[2];
  const float* bk = (const float*)d_in[3];
  const float* Wq = (const float*)d_in[4];
  const float* bq = (const float*)d_in[5];
  const float* Wv = (const float*)d_in[6];
  const float* bv = (const float*)d_in[7];
  const float* Wr = (const float*)d_in[8];
  const float* br = (const float*)d_in[9];
  float* out = (float*)d_out;

  cudaFuncSetAttribute(proj_kernel, cudaFuncAttributeMaxDynamicSharedMemorySize, SMEM_PROJ);
  cudaFuncSetAttribute(out_kernel,  cudaFuncAttributeMaxDynamicSharedMemorySize, SMEM_OUT);

  dim3 grid(NT, NB);
  proj_kernel<<<grid, 512, SMEM_PROJ>>>(x, Wk, bk, Wq, bq, Wv, bv);
  finalize_kernel<<<NB, 512>>>(CLS, Wr, out);
  out_kernel<<<grid, 512, SMEM_OUT>>>(br, out);
}

// round 8
// speedup vs baseline: 2.4148x; 1.0040x over previous
#include <cuda_runtime.h>
#include <cstdint>

// EfficientAttention3D — mma.sync tf32 + ldmatrix (R8).
//   proj_kernel : 16 warps, warp tile 32x32, all operand loads via ldmatrix.x4.
//                 x staged transposed [l][c] with chunk-rotation (conflict-free
//                 column stores + ldmatrix reads). Q/K/V GEMMs; q-softmax -> g_qs,
//                 exp(K) -> es, V -> vs, per-head context MMA -> g_part[elem][tile].
//   finalize    : coalesced warp-per-element tile reduction, CLS terms, normalize,
//                 context_last & CLS_out, M = Wr @ blockdiag(ctx^T).
//   out_kernel  : attention = M @ qs + br (ldmatrix path too).

#define NB   2
#define CH   128
#define LEN  65536
#define TL   128
#define NT   (LEN/TL)
#define NCLS 4
#define PIT  132

// proj smem (float offsets): xs rotated 128*128, ws/es pitch-132
#define S_XS 0
#define S_WS 16384
#define S_ES 33280
#define S_RS 50176
#define SMEM_PROJ ((50176+512)*4)        // 202752 B
#define SMEM_OUT  ((16384+16896)*4)      // 133120 B

__device__ float g_qs[(size_t)NB*CH*LEN];
__device__ float g_part[(size_t)NB*2176*NT];   // [n][elem][tile]
__device__ float g_M[NB*CH*CH];

__device__ __forceinline__ float tf32r(float f){
  uint32_t u; asm("cvt.rna.tf32.f32 %0, %1;":"=r"(u):"f"(f)); return __uint_as_float(u);
}
__device__ __forceinline__ uint32_t smem_u32(const void* p){
  uint32_t a; asm("{ .reg .u64 t; cvta.to.shared.u64 t, %1; cvt.u32.u64 %0, t; }":"=r"(a):"l"(p)); return a;
}
__device__ __forceinline__ void mma8(float d[4], const uint32_t a[4], const uint32_t b[2]){
  asm volatile("mma.sync.aligned.m16n8k8.row.col.f32.tf32.tf32.f32 "
    "{%0,%1,%2,%3}, {%4,%5,%6,%7}, {%8,%9}, {%0,%1,%2,%3};"
    : "+f"(d[0]),"+f"(d[1]),"+f"(d[2]),"+f"(d[3])
    : "r"(a[0]),"r"(a[1]),"r"(a[2]),"r"(a[3]),"r"(b[0]),"r"(b[1]));
}
__device__ __forceinline__ void ldsm4(uint32_t* r, uint32_t a){
  asm volatile("ldmatrix.sync.aligned.m8n8.x4.shared.b16 {%0,%1,%2,%3}, [%4];"
    : "=r"(r[0]),"=r"(r[1]),"=r"(r[2]),"=r"(r[3]) : "r"(a));
}

// stage row-major 128x128 into pitch-PIT smem, tf32-rounded (512 threads)
__device__ __forceinline__ void stageW(float* dst, const float* __restrict__ src, int tid, int srcPitch){
  for (int idx=tid; idx<4096; idx+=512){
    int o=idx>>5, c4=(idx&31)*4;
    float4 w = *(const float4*)(src + (size_t)o*srcPitch + c4);
    w.x=tf32r(w.x); w.y=tf32r(w.y); w.z=tf32r(w.z); w.w=tf32r(w.w);
    *(float4*)(dst + o*PIT + c4) = w;
  }
}
// stage [c][l]-strided source transposed into rotated [l][c] layout
__device__ __forceinline__ void stageXrot(float* xs, const float* __restrict__ src, int tid, int srcPitch){
#pragma unroll 4
  for (int e=tid; e<16384; e+=512){
    int c = e>>7, l = e&127;
    float v = tf32r(__ldg(src + (size_t)c*srcPitch + l));
    xs[l*128 + (((((c>>2)+l)&31)<<2) | (c&3))] = v;
  }
}

// A: ws row-major [128][PIT]; B: xs rotated [l][128]. Warp tile 32x32.
__device__ __forceinline__ void gemmL(uint32_t wsb, uint32_t xsb, float acc[2][4][4],
                                      int wr, int wc, int lane)
{
#pragma unroll
  for (int m=0;m<2;m++)
#pragma unroll
    for (int n=0;n<4;n++)
#pragma unroll
      for (int j=0;j<4;j++) acc[m][n][j]=0.f;
  const int t15 = lane & 15, t16 = lane >> 4;
  const uint32_t aaddr0 = wsb + (uint32_t)((wr*32 + t15)*PIT + t16*4)*4;
  const uint32_t aaddr1 = aaddr0 + 16*PIT*4;
  const int rowb0 = wc*32 + t15, rowb1 = rowb0 + 16;
  const uint32_t bbase0 = xsb + (uint32_t)rowb0*512;
  const uint32_t bbase1 = xsb + (uint32_t)rowb1*512;
  const int cb0 = t16 + rowb0, cb1 = t16 + rowb1;
#pragma unroll
  for (int k=0;k<16;k++){
    uint32_t a0[4], a1[4], b0[4], b1[4], bb[2];
    ldsm4(a0, aaddr0 + k*32);
    ldsm4(a1, aaddr1 + k*32);
    ldsm4(b0, bbase0 + (uint32_t)(((cb0 + 2*k)&31)<<4));
    ldsm4(b1, bbase1 + (uint32_t)(((cb1 + 2*k)&31)<<4));
    bb[0]=b0[0]; bb[1]=b0[2]; mma8(acc[0][0], a0, bb); mma8(acc[1][0], a1, bb);
    bb[0]=b0[1]; bb[1]=b0[3]; mma8(acc[0][1], a0, bb); mma8(acc[1][1], a1, bb);
    bb[0]=b1[0]; bb[1]=b1[2]; mma8(acc[0][2], a0, bb); mma8(acc[1][2], a1, bb);
    bb[0]=b1[1]; bb[1]=b1[3]; mma8(acc[0][3], a0, bb); mma8(acc[1][3], a1, bb);
  }
}

extern "C" __global__ void __launch_bounds__(512,1)
proj_kernel(const float* __restrict__ x,
            const float* __restrict__ Wk, const float* __restrict__ bk,
            const float* __restrict__ Wq, const float* __restrict__ bq,
            const float* __restrict__ Wv, const float* __restrict__ bv)
{
  extern __shared__ float sm[];
  float* xs = sm + S_XS;
  float* ws = sm + S_WS;   // Wq -> Wv -> vs
  float* es = sm + S_ES;   // Wk -> exp(K)
  float* rs = sm + S_RS;
  const int tid = threadIdx.x, wid = tid>>5, lane = tid&31;
  const int wr = wid&3, wc = wid>>2, lr = lane>>2, lc = lane&3;
  const int n = blockIdx.y, l0 = blockIdx.x*TL;
  const uint32_t xsb = smem_u32(xs), wsb = smem_u32(ws), esb = smem_u32(es);

  stageXrot(xs, x + (size_t)n*CH*LEN + l0, tid, LEN);
  stageW(ws, Wq, tid, CH);
  stageW(es, Wk, tid, CH);
  __syncthreads();

  float acc[2][4][4];

  // ---- Q: GEMM + 16-channel softmax ----
  gemmL(wsb, xsb, acc, wr, wc, lane);
  {
    float* qg = g_qs + (size_t)n*CH*LEN + l0;
#pragma unroll
    for (int m=0;m<2;m++){
      const int rt = wr*32 + m*16 + lr, rb = rt + 8;
      const float bt = __ldg(bq + rt), bb = __ldg(bq + rb);
      float e[4][4], s0[4], s1[4];
#pragma unroll
      for (int nn=0;nn<4;nn++){
        e[nn][0]=__expf(acc[m][nn][0]+bt); e[nn][1]=__expf(acc[m][nn][1]+bt);
        e[nn][2]=__expf(acc[m][nn][2]+bb); e[nn][3]=__expf(acc[m][nn][3]+bb);
        s0[nn]=e[nn][0]+e[nn][2]; s1[nn]=e[nn][1]+e[nn][3];
      }
#pragma unroll
      for (int nn=0;nn<4;nn++){
        s0[nn] += __shfl_xor_sync(0xffffffffu, s0[nn], 4);
        s0[nn] += __shfl_xor_sync(0xffffffffu, s0[nn], 8);
        s0[nn] += __shfl_xor_sync(0xffffffffu, s0[nn], 16);
        s1[nn] += __shfl_xor_sync(0xffffffffu, s1[nn], 4);
        s1[nn] += __shfl_xor_sync(0xffffffffu, s1[nn], 8);
        s1[nn] += __shfl_xor_sync(0xffffffffu, s1[nn], 16);
        float i0 = __frcp_rn(s0[nn]), i1 = __frcp_rn(s1[nn]);
        int c = wc*32 + nn*8 + lc*2;
        *(float2*)(qg + (size_t)rt*LEN + c) = make_float2(e[nn][0]*i0, e[nn][1]*i1);
        *(float2*)(qg + (size_t)rb*LEN + c) = make_float2(e[nn][2]*i0, e[nn][3]*i1);
      }
    }
  }

  // ---- K: GEMM from es(Wk) ----
  gemmL(esb, xsb, acc, wr, wc, lane);
  __syncthreads();                // all reads of ws(Wq) & es(Wk) done

  // K epilogue -> es = exp(K); concurrently stage Wv -> ws
#pragma unroll
  for (int m=0;m<2;m++){
    const int rt = wr*32 + m*16 + lr, rb = rt + 8;
    const float bt = __ldg(bk + rt), bb = __ldg(bk + rb);
    float rowt=0.f, rowb=0.f;
#pragma unroll
    for (int nn=0;nn<4;nn++){
      float e0=__expf(acc[m][nn][0]+bt), e1=__expf(acc[m][nn][1]+bt);
      float e2=__expf(acc[m][nn][2]+bb), e3=__expf(acc[m][nn][3]+bb);
      rowt += e0+e1; rowb += e2+e3;
      int c = wc*32 + nn*8 + lc*2;
      *(float2*)(es + rt*PIT + c) = make_float2(tf32r(e0), tf32r(e1));
      *(float2*)(es + rb*PIT + c) = make_float2(tf32r(e2), tf32r(e3));
    }
    rowt += __shfl_xor_sync(0xffffffffu, rowt, 1);
    rowt += __shfl_xor_sync(0xffffffffu, rowt, 2);
    rowb += __shfl_xor_sync(0xffffffffu, rowb, 1);
    rowb += __shfl_xor_sync(0xffffffffu, rowb, 2);
    if (lc == 0){ rs[rt*4+wc]=rowt; rs[rb*4+wc]=rowb; }
  }
  stageW(ws, Wv, tid, CH);
  __syncthreads();

  // ---- V: GEMM -> vs (= ws after sync) ----
  gemmL(wsb, xsb, acc, wr, wc, lane);
  __syncthreads();
  float* vs = ws;
#pragma unroll
  for (int m=0;m<2;m++){
    const int rt = wr*32 + m*16 + lr, rb = rt + 8;
    const float bt = __ldg(bv + rt), bb = __ldg(bv + rb);
#pragma unroll
    for (int nn=0;nn<4;nn++){
      int c = wc*32 + nn*8 + lc*2;
      *(float2*)(vs + rt*PIT + c) = make_float2(tf32r(acc[m][nn][0]+bt), tf32r(acc[m][nn][1]+bt));
      *(float2*)(vs + rb*PIT + c) = make_float2(tf32r(acc[m][nn][2]+bb), tf32r(acc[m][nn][3]+bb));
    }
  }
  __syncthreads();

  // ---- context: ctx[h] = E_h @ V_h^T (16x16, K=128 split over 2 warps) ----
  float* pb = g_part + (size_t)n*2176*NT + blockIdx.x;
  float* cbuf = xs;  // xs free now
  {
    const int h = wid>>1, kh = wid&1;
    const int t15 = lane&15, t16 = lane>>4;
    uint32_t ae = esb + (uint32_t)((h*16 + t15)*PIT + kh*64 + t16*4)*4;
    uint32_t av = smem_u32(vs) + (uint32_t)((h*16 + t15)*PIT + kh*64 + t16*4)*4;
    float ca[2][4];
#pragma unroll
    for (int nt=0;nt<2;nt++)
#pragma unroll
      for (int j=0;j<4;j++) ca[nt][j]=0.f;
#pragma unroll
    for (int k=0;k<8;k++){
      uint32_t a[4], b[4], bb[2];
      ldsm4(a, ae + k*32);
      ldsm4(b, av + k*32);
      bb[0]=b[0]; bb[1]=b[2]; mma8(ca[0], a, bb);
      bb[0]=b[1]; bb[1]=b[3]; mma8(ca[1], a, bb);
    }
    if (kh == 1){
#pragma unroll
      for (int nt=0;nt<2;nt++){
        int v = nt*8 + lc*2;
        *(float2*)(cbuf + h*256 + lr*16     + v) = make_float2(ca[nt][0], ca[nt][1]);
        *(float2*)(cbuf + h*256 + (lr+8)*16 + v) = make_float2(ca[nt][2], ca[nt][3]);
      }
    }
    __syncthreads();
    if (kh == 0){
#pragma unroll
      for (int nt=0;nt<2;nt++){
        int v = nt*8 + lc*2;
        pb[(size_t)(h*256 + lr*16 + v    )*NT] = ca[nt][0] + cbuf[h*256 + lr*16 + v];
        pb[(size_t)(h*256 + lr*16 + v + 1)*NT] = ca[nt][1] + cbuf[h*256 + lr*16 + v + 1];
        pb[(size_t)(h*256 + (lr+8)*16 + v    )*NT] = ca[nt][2] + cbuf[h*256 + (lr+8)*16 + v];
        pb[(size_t)(h*256 + (lr+8)*16 + v + 1)*NT] = ca[nt][3] + cbuf[h*256 + (lr+8)*16 + v + 1];
      }
    }
  }
  if (tid < CH)
    pb[(size_t)(2048 + tid)*NT] = rs[tid*4] + rs[tid*4+1] + rs[tid*4+2] + rs[tid*4+3];
}

// ---------------- finalize (unchanged from R7) ----------------
extern "C" __global__ void __launch_bounds__(512,1)
finalize_kernel(const float* __restrict__ CLS,
                const float* __restrict__ Wr,
                float* __restrict__ out)
{
  __shared__ float ctx[2048];
  __shared__ float Ssum[128];
  __shared__ float ecls[512];
  __shared__ float clsv[512];
  __shared__ float cn[2048];
  const int n = blockIdx.x;
  const int tid = threadIdx.x, wid = tid>>5, lane = tid&31;

  for (int o = wid; o < 2176; o += 16){
    const float* p = g_part + ((size_t)n*2176 + o)*NT + lane*4;
    float s = 0.f;
#pragma unroll
    for (int i=0;i<4;i++){ float4 v = *(const float4*)(p + i*128); s += v.x+v.y+v.z+v.w; }
    s += __shfl_xor_sync(0xffffffffu, s, 16);
    s += __shfl_xor_sync(0xffffffffu, s, 8);
    s += __shfl_xor_sync(0xffffffffu, s, 4);
    s += __shfl_xor_sync(0xffffffffu, s, 2);
    s += __shfl_xor_sync(0xffffffffu, s, 1);
    if (lane == 0){ if (o < 2048) ctx[o] = s; else Ssum[o-2048] = s; }
  }
  if (tid < 512){
    float v = CLS[(size_t)n*CH*NCLS + tid];
    clsv[tid]=v; ecls[tid]=__expf(v);
  }
  __syncthreads();
  if (tid < 128){
    float s = Ssum[tid];
#pragma unroll
    for (int j=0;j<NCLS;j++) s += ecls[tid*NCLS+j];
    Ssum[tid]=s;
  }
  __syncthreads();
  for (int idx=tid; idx<2048; idx+=512){
    int h=idx>>8, k=(idx>>4)&15, v=idx&15;
    float s=ctx[idx];
#pragma unroll
    for (int j=0;j<NCLS;j++) s += ecls[(h*16+k)*NCLS+j]*clsv[(h*16+v)*NCLS+j];
    cn[idx] = s / Ssum[h*16+k];
  }
  __syncthreads();
  if (tid < 256) out[(size_t)NB*CH*LEN + n*256 + tid] = cn[7*256 + tid];
  if (tid < 64){
    int v=tid>>2, j=tid&3;
    float se=0.f, a=0.f;
#pragma unroll
    for (int k=0;k<16;k++){
      float e = ecls[(112+k)*NCLS + j];
      se += e;
      a  += cn[7*256 + k*16 + v]*e;
    }
    out[(size_t)NB*CH*LEN + (size_t)NB*256 + n*64 + v*4 + j] = a/se;
  }
  for (int idx=tid; idx<CH*CH; idx+=512){
    int o=idx>>7, c=idx&127, h=c>>4, k=c&15;
    float m=0.f;
#pragma unroll
    for (int v=0;v<16;v++) m += Wr[o*CH + h*16+v]*cn[h*256 + k*16 + v];
    g_M[(size_t)n*CH*CH + idx] = m;
  }
}

// ---------------- out: attention = M @ qs + br ----------------
extern "C" __global__ void __launch_bounds__(512,1)
out_kernel(const float* __restrict__ br, float* __restrict__ out)
{
  extern __shared__ float sm[];
  float* xs = sm;               // qs rotated
  float* ms = sm + 16384;       // M pitch-132
  const int tid = threadIdx.x, wid = tid>>5, lane = tid&31;
  const int wr = wid&3, wc = wid>>2, lr = lane>>2, lc = lane&3;
  const int n = blockIdx.y, l0 = blockIdx.x*TL;

  stageXrot(xs, g_qs + (size_t)n*CH*LEN + l0, tid, LEN);
  stageW(ms, g_M + (size_t)n*CH*CH, tid, CH);
  __syncthreads();

  float acc[2][4][4];
  gemmL(smem_u32(ms), smem_u32(xs), acc, wr, wc, lane);

  float* og = out + (size_t)n*CH*LEN + l0;
#pragma unroll
  for (int m=0;m<2;m++){
    const int rt = wr*32 + m*16 + lr, rb = rt + 8;
    const float bt = __ldg(br + rt), bb = __ldg(br + rb);
#pragma unroll
    for (int nn=0;nn<4;nn++){
      int c = wc*32 + nn*8 + lc*2;
      *(float2*)(og + (size_t)rt*LEN + c) = make_float2(acc[m][nn][0]+bt, acc[m][nn][1]+bt);
      *(float2*)(og + (size_t)rb*LEN + c) = make_float2(acc[m][nn][2]+bb, acc[m][nn][3]+bb);
    }
  }
}

extern "C" void kernel_launch(void* const* d_in, const int* in_sizes, int n_in,
                              void* d_out, int out_size)
{
  const float* x  = (const float*)d_in[0];
  const float* CLS= (const float*)d_in[1];
  const float* Wk = (const float*)d_in[2];
  const float* bk = (const float*)d_in[3];
  const float* Wq = (const float*)d_in[4];
  const float* bq = (const float*)d_in[5];
  const float* Wv = (const float*)d_in[6];
  const float* bv = (const float*)d_in[7];
  const float* Wr = (const float*)d_in[8];
  const float* br = (const float*)d_in[9];
  float* out = (float*)d_out;

  cudaFuncSetAttribute(proj_kernel, cudaFuncAttributeMaxDynamicSharedMemorySize, SMEM_PROJ);
  cudaFuncSetAttribute(out_kernel,  cudaFuncAttributeMaxDynamicSharedMemorySize, SMEM_OUT);

  dim3 grid(NT, NB);
  proj_kernel<<<grid, 512, SMEM_PROJ>>>(x, Wk, bk, Wq, bq, Wv, bv);
  finalize_kernel<<<NB, 512>>>(CLS, Wr, out);
  out_kernel<<<grid, 512, SMEM_OUT>>>(br, out);
}

// round 9
// speedup vs baseline: 2.9236x; 1.2107x over previous
#include <cuda_runtime.h>
#include <cuda_fp16.h>
#include <cstdint>

// EfficientAttention3D — fp16 mma.sync m16n8k16 (R9).
//   proj_kernel : 16 warps, warp tile 32x32. x/W staged fp16 in rotated-chunk
//                 layout; Q+K GEMMs back-to-back (dual acc, 2x ILP); epilogues:
//                 q-softmax -> fp16 rotated tile -> g_qs (raw copy), exp(K)->es,
//                 V->vs (fp16), per-head context MMA -> g_part[elem][tile].
//   finalize    : unchanged (fp32).
//   out_kernel  : attention = M @ qs + br; qs staged by raw 32KB copy.

#define NB   2
#define CH   128
#define LEN  65536
#define TL   128
#define NT   (LEN/TL)
#define NCLS 4

// proj smem byte offsets
#define B_XS 0          // 32KB x tile [l][ch] fp16 rotated
#define B_WA 32768      // 32KB Wq -> qstage -> Wv -> vs
#define B_WB 65536      // 32KB Wk -> es
#define B_RS 98304      // 2KB rowsum partials
#define SMEM_PROJ 100352
#define SMEM_OUT  65536

__device__ __align__(16) __half g_qs[(size_t)NB*NT*16384];   // per-tile rotated [l][ch], 32MB
__device__ float g_part[(size_t)NB*2176*NT];                 // [n][elem][tile]
__device__ float g_M[NB*CH*CH];

__device__ __forceinline__ uint32_t smem_u32(const void* p){
  uint32_t a; asm("{ .reg .u64 t; cvta.to.shared.u64 t, %1; cvt.u32.u64 %0, t; }":"=r"(a):"l"(p)); return a;
}
__device__ __forceinline__ void mma16(float d[4], const uint32_t a[4], uint32_t b0, uint32_t b1){
  asm volatile("mma.sync.aligned.m16n8k16.row.col.f32.f16.f16.f32 "
    "{%0,%1,%2,%3}, {%4,%5,%6,%7}, {%8,%9}, {%0,%1,%2,%3};"
    : "+f"(d[0]),"+f"(d[1]),"+f"(d[2]),"+f"(d[3])
    : "r"(a[0]),"r"(a[1]),"r"(a[2]),"r"(a[3]),"r"(b0),"r"(b1));
}
__device__ __forceinline__ void ldsm4(uint32_t* r, uint32_t a){
  asm volatile("ldmatrix.sync.aligned.m8n8.x4.shared.b16 {%0,%1,%2,%3}, [%4];"
    : "=r"(r[0]),"=r"(r[1]),"=r"(r[2]),"=r"(r[3]) : "r"(a));
}

// rotated-chunk layout: element (r,c) of a [R][128] fp16 tile lives at
//   r*256 + (((c>>3)+r)&15)*16 + (c&7)*2
__device__ __forceinline__ void stH2(__half* b, int r, int c, float v0, float v1){
  *(__half2*)((char*)b + r*256 + ((((c>>3)+r)&15)<<4) + (c&7)*2) = __floats2half2_rn(v0,v1);
}

// stage [c][l] fp32 (stride srcPitch) transposed -> [l][c] fp16 rotated
__device__ __forceinline__ void stageXT(__half* xs, const float* __restrict__ src, int tid, size_t srcPitch){
  const int l = tid&127, cg = tid>>7;
#pragma unroll
  for (int pass=0; pass<4; pass++){
    const int c0 = pass*32 + cg*8;
    __half h[8];
#pragma unroll
    for (int i=0;i<8;i++) h[i] = __float2half(__ldg(src + (size_t)(c0+i)*srcPitch + l));
    *(uint4*)((char*)xs + l*256 + ((((c0>>3)+l)&15)<<4)) = *(uint4*)h;
  }
}
// stage row-major [128][srcPitch] fp32 -> [o][k] fp16 rotated
__device__ __forceinline__ void stageWH(__half* ws, const float* __restrict__ src, int tid, int srcPitch){
  const int o = tid>>4, ch = tid&15;
#pragma unroll
  for (int pass=0; pass<4; pass++){
    const int oo = pass*32 + o;
    const float* p = src + (size_t)oo*srcPitch + ch*8;
    float4 f0 = *(const float4*)p, f1 = *(const float4*)(p+4);
    __half h[8] = {__float2half(f0.x),__float2half(f0.y),__float2half(f0.z),__float2half(f0.w),
                   __float2half(f1.x),__float2half(f1.y),__float2half(f1.z),__float2half(f1.w)};
    *(uint4*)((char*)ws + oo*256 + (((ch+oo)&15)<<4)) = *(uint4*)h;
  }
}

// A: ws [128 m][128 k] fp16 rotated; B: xs [128 n][128 k] fp16 rotated. Warp tile 32x32.
__device__ __forceinline__ void gemm16(uint32_t wsb, uint32_t xsb, float acc[2][4][4],
                                       int wr, int wc, int lane)
{
#pragma unroll
  for (int m=0;m<2;m++)
#pragma unroll
    for (int n=0;n<4;n++)
#pragma unroll
      for (int j=0;j<4;j++) acc[m][n][j]=0.f;
  const int ar0 = wr*32 + (lane&15), ar1 = ar0 + 16;
  const int ach = lane>>4;
  const uint32_t a0b = wsb + ar0*256, a1b = wsb + ar1*256;
  const int br0 = wc*32 + (lane&7) + ((lane>>4)<<3), br1 = br0 + 16;
  const int bch = (lane>>3)&1;
  const uint32_t b0b = xsb + br0*256, b1b = xsb + br1*256;
#pragma unroll
  for (int k=0;k<8;k++){
    uint32_t a0[4],a1[4],b0[4],b1[4];
    ldsm4(a0, a0b + (((2*k+ach+ar0)&15)<<4));
    ldsm4(a1, a1b + (((2*k+ach+ar1)&15)<<4));
    ldsm4(b0, b0b + (((2*k+bch+br0)&15)<<4));
    ldsm4(b1, b1b + (((2*k+bch+br1)&15)<<4));
    mma16(acc[0][0], a0, b0[0], b0[1]); mma16(acc[1][0], a1, b0[0], b0[1]);
    mma16(acc[0][1], a0, b0[2], b0[3]); mma16(acc[1][1], a1, b0[2], b0[3]);
    mma16(acc[0][2], a0, b1[0], b1[1]); mma16(acc[1][2], a1, b1[0], b1[1]);
    mma16(acc[0][3], a0, b1[2], b1[3]); mma16(acc[1][3], a1, b1[2], b1[3]);
  }
}

extern "C" __global__ void __launch_bounds__(512,1)
proj_kernel(const float* __restrict__ x,
            const float* __restrict__ Wk, const float* __restrict__ bk,
            const float* __restrict__ Wq, const float* __restrict__ bq,
            const float* __restrict__ Wv, const float* __restrict__ bv)
{
  extern __shared__ char smb[];
  __half* xs = (__half*)(smb + B_XS);
  __half* wA = (__half*)(smb + B_WA);   // Wq -> qstage -> Wv -> vs
  __half* wB = (__half*)(smb + B_WB);   // Wk -> es
  float*  rs = (float*)(smb + B_RS);
  const int tid = threadIdx.x, wid = tid>>5, lane = tid&31;
  const int wr = wid&3, wc = wid>>2, lr = lane>>2, lc = lane&3;
  const int n = blockIdx.y, tile = blockIdx.x, l0 = tile*TL;
  const uint32_t xsb = smem_u32(xs), wAb = smem_u32(wA), wBb = smem_u32(wB);

  stageXT(xs, x + (size_t)n*CH*LEN + l0, tid, LEN);
  stageWH(wA, Wq, tid, CH);
  stageWH(wB, Wk, tid, CH);
  __syncthreads();

  float accQ[2][4][4], accK[2][4][4];
  gemm16(wAb, xsb, accQ, wr, wc, lane);
  gemm16(wBb, xsb, accK, wr, wc, lane);
  __syncthreads();   // all reads of wA/wB done

  // ---- Q epilogue: exp + 16-channel softmax -> wA as [l][ch] fp16 rotated ----
  {
    __half* qh = wA;
#pragma unroll
    for (int m=0;m<2;m++){
      const int rt = wr*32 + m*16 + lr, rb = rt + 8;
      const float bt = __ldg(bq + rt), bb = __ldg(bq + rb);
      float e[4][4], s0[4], s1[4];
#pragma unroll
      for (int nn=0;nn<4;nn++){
        e[nn][0]=__expf(accQ[m][nn][0]+bt); e[nn][1]=__expf(accQ[m][nn][1]+bt);
        e[nn][2]=__expf(accQ[m][nn][2]+bb); e[nn][3]=__expf(accQ[m][nn][3]+bb);
        s0[nn]=e[nn][0]+e[nn][2]; s1[nn]=e[nn][1]+e[nn][3];
      }
#pragma unroll
      for (int nn=0;nn<4;nn++){
        s0[nn] += __shfl_xor_sync(0xffffffffu, s0[nn], 4);
        s0[nn] += __shfl_xor_sync(0xffffffffu, s0[nn], 8);
        s0[nn] += __shfl_xor_sync(0xffffffffu, s0[nn], 16);
        s1[nn] += __shfl_xor_sync(0xffffffffu, s1[nn], 4);
        s1[nn] += __shfl_xor_sync(0xffffffffu, s1[nn], 8);
        s1[nn] += __shfl_xor_sync(0xffffffffu, s1[nn], 16);
        float i0 = __frcp_rn(s0[nn]), i1 = __frcp_rn(s1[nn]);
        int c = wc*32 + nn*8 + lc*2;
        // transpose: value (channel rt, col c) -> row l=c, col ch=rt
        *(__half*)((char*)qh + c*256     + ((((rt>>3)+c  )&15)<<4) + (rt&7)*2) = __float2half(e[nn][0]*i0);
        *(__half*)((char*)qh + (c+1)*256 + ((((rt>>3)+c+1)&15)<<4) + (rt&7)*2) = __float2half(e[nn][1]*i1);
        *(__half*)((char*)qh + c*256     + ((((rb>>3)+c  )&15)<<4) + (rb&7)*2) = __float2half(e[nn][2]*i0);
        *(__half*)((char*)qh + (c+1)*256 + ((((rb>>3)+c+1)&15)<<4) + (rb&7)*2) = __float2half(e[nn][3]*i1);
      }
    }
  }
  // ---- K epilogue: exp -> wB = es [ch][l] fp16 rotated (+ rowsums) ----
#pragma unroll
  for (int m=0;m<2;m++){
    const int rt = wr*32 + m*16 + lr, rb = rt + 8;
    const float bt = __ldg(bk + rt), bb = __ldg(bk + rb);
    float rowt=0.f, rowb=0.f;
#pragma unroll
    for (int nn=0;nn<4;nn++){
      float e0=__expf(accK[m][nn][0]+bt), e1=__expf(accK[m][nn][1]+bt);
      float e2=__expf(accK[m][nn][2]+bb), e3=__expf(accK[m][nn][3]+bb);
      rowt += e0+e1; rowb += e2+e3;
      int c = wc*32 + nn*8 + lc*2;
      stH2(wB, rt, c, e0, e1);
      stH2(wB, rb, c, e2, e3);
    }
    rowt += __shfl_xor_sync(0xffffffffu, rowt, 1);
    rowt += __shfl_xor_sync(0xffffffffu, rowt, 2);
    rowb += __shfl_xor_sync(0xffffffffu, rowb, 1);
    rowb += __shfl_xor_sync(0xffffffffu, rowb, 2);
    if (lc == 0){ rs[rt*4+wc]=rowt; rs[rb*4+wc]=rowb; }
  }
  __syncthreads();

  // ---- copy qstage -> g_qs (raw, coalesced) ----
  {
    uint4* dst = (uint4*)g_qs + (size_t)(n*NT + tile)*2048;
    const uint4* srcq = (const uint4*)wA;
    for (int i=tid; i<2048; i+=512) dst[i] = srcq[i];
  }
  __syncthreads();   // wA reads done
  stageWH(wA, Wv, tid, CH);
  __syncthreads();

  // ---- V GEMM -> vs (= wA after sync) ----
  gemm16(wAb, xsb, accQ, wr, wc, lane);
  __syncthreads();
#pragma unroll
  for (int m=0;m<2;m++){
    const int rt = wr*32 + m*16 + lr, rb = rt + 8;
    const float bt = __ldg(bv + rt), bb = __ldg(bv + rb);
#pragma unroll
    for (int nn=0;nn<4;nn++){
      int c = wc*32 + nn*8 + lc*2;
      stH2(wA, rt, c, accQ[m][nn][0]+bt, accQ[m][nn][1]+bt);
      stH2(wA, rb, c, accQ[m][nn][2]+bb, accQ[m][nn][3]+bb);
    }
  }
  __syncthreads();

  // ---- context: ctx[h] = E_h @ V_h^T (16x16, K=128 split over 2 warps) ----
  float* pb = g_part + (size_t)n*2176*NT + tile;
  float* cbuf = (float*)xs;  // xs free now
  {
    const int h = wid>>1, kh = wid&1;
    const int ar = h*16 + (lane&15);
    const int ach = (lane>>4);
    const int brr = h*16 + (lane&7) + ((lane>>4)<<3);
    const int bch = (lane>>3)&1;
    const uint32_t ab = wBb + ar*256;
    const uint32_t bbv = wAb + brr*256;
    float ca[2][4];
#pragma unroll
    for (int nt=0;nt<2;nt++)
#pragma unroll
      for (int j=0;j<4;j++) ca[nt][j]=0.f;
#pragma unroll
    for (int ks=0;ks<4;ks++){
      const int c2 = kh*8 + ks*2;
      uint32_t a[4], b[4];
      ldsm4(a, ab  + (((c2+ach+ar )&15)<<4));
      ldsm4(b, bbv + (((c2+bch+brr)&15)<<4));
      mma16(ca[0], a, b[0], b[1]);
      mma16(ca[1], a, b[2], b[3]);
    }
    if (kh == 1){
#pragma unroll
      for (int nt=0;nt<2;nt++){
        int v = nt*8 + lc*2;
        *(float2*)(cbuf + h*256 + lr*16     + v) = make_float2(ca[nt][0], ca[nt][1]);
        *(float2*)(cbuf + h*256 + (lr+8)*16 + v) = make_float2(ca[nt][2], ca[nt][3]);
      }
    }
    __syncthreads();
    if (kh == 0){
#pragma unroll
      for (int nt=0;nt<2;nt++){
        int v = nt*8 + lc*2;
        pb[(size_t)(h*256 + lr*16 + v    )*NT] = ca[nt][0] + cbuf[h*256 + lr*16 + v];
        pb[(size_t)(h*256 + lr*16 + v + 1)*NT] = ca[nt][1] + cbuf[h*256 + lr*16 + v + 1];
        pb[(size_t)(h*256 + (lr+8)*16 + v    )*NT] = ca[nt][2] + cbuf[h*256 + (lr+8)*16 + v];
        pb[(size_t)(h*256 + (lr+8)*16 + v + 1)*NT] = ca[nt][3] + cbuf[h*256 + (lr+8)*16 + v + 1];
      }
    }
  }
  if (tid < CH)
    pb[(size_t)(2048 + tid)*NT] = rs[tid*4] + rs[tid*4+1] + rs[tid*4+2] + rs[tid*4+3];
}

// ---------------- finalize (unchanged) ----------------
extern "C" __global__ void __launch_bounds__(512,1)
finalize_kernel(const float* __restrict__ CLS,
                const float* __restrict__ Wr,
                float* __restrict__ out)
{
  __shared__ float ctx[2048];
  __shared__ float Ssum[128];
  __shared__ float ecls[512];
  __shared__ float clsv[512];
  __shared__ float cn[2048];
  const int n = blockIdx.x;
  const int tid = threadIdx.x, wid = tid>>5, lane = tid&31;

  for (int o = wid; o < 2176; o += 16){
    const float* p = g_part + ((size_t)n*2176 + o)*NT + lane*4;
    float s = 0.f;
#pragma unroll
    for (int i=0;i<4;i++){ float4 v = *(const float4*)(p + i*128); s += v.x+v.y+v.z+v.w; }
    s += __shfl_xor_sync(0xffffffffu, s, 16);
    s += __shfl_xor_sync(0xffffffffu, s, 8);
    s += __shfl_xor_sync(0xffffffffu, s, 4);
    s += __shfl_xor_sync(0xffffffffu, s, 2);
    s += __shfl_xor_sync(0xffffffffu, s, 1);
    if (lane == 0){ if (o < 2048) ctx[o] = s; else Ssum[o-2048] = s; }
  }
  if (tid < 512){
    float v = CLS[(size_t)n*CH*NCLS + tid];
    clsv[tid]=v; ecls[tid]=__expf(v);
  }
  __syncthreads();
  if (tid < 128){
    float s = Ssum[tid];
#pragma unroll
    for (int j=0;j<NCLS;j++) s += ecls[tid*NCLS+j];
    Ssum[tid]=s;
  }
  __syncthreads();
  for (int idx=tid; idx<2048; idx+=512){
    int h=idx>>8, k=(idx>>4)&15, v=idx&15;
    float s=ctx[idx];
#pragma unroll
    for (int j=0;j<NCLS;j++) s += ecls[(h*16+k)*NCLS+j]*clsv[(h*16+v)*NCLS+j];
    cn[idx] = s / Ssum[h*16+k];
  }
  __syncthreads();
  if (tid < 256) out[(size_t)NB*CH*LEN + n*256 + tid] = cn[7*256 + tid];
  if (tid < 64){
    int v=tid>>2, j=tid&3;
    float se=0.f, a=0.f;
#pragma unroll
    for (int k=0;k<16;k++){
      float e = ecls[(112+k)*NCLS + j];
      se += e;
      a  += cn[7*256 + k*16 + v]*e;
    }
    out[(size_t)NB*CH*LEN + (size_t)NB*256 + n*64 + v*4 + j] = a/se;
  }
  for (int idx=tid; idx<CH*CH; idx+=512){
    int o=idx>>7, c=idx&127, h=c>>4, k=c&15;
    float m=0.f;
#pragma unroll
    for (int v=0;v<16;v++) m += Wr[o*CH + h*16+v]*cn[h*256 + k*16 + v];
    g_M[(size_t)n*CH*CH + idx] = m;
  }
}

// ---------------- out: attention = M @ qs + br ----------------
extern "C" __global__ void __launch_bounds__(512,1)
out_kernel(const float* __restrict__ br, float* __restrict__ out)
{
  extern __shared__ char smb[];
  __half* xs = (__half*)smb;            // qs tile (raw copy, rotated [l][ch])
  __half* ms = (__half*)(smb + 32768);  // M fp16 rotated
  const int tid = threadIdx.x, wid = tid>>5, lane = tid&31;
  const int wr = wid&3, wc = wid>>2, lr = lane>>2, lc = lane&3;
  const int n = blockIdx.y, tile = blockIdx.x, l0 = tile*TL;

  {
    uint4* dst = (uint4*)xs;
    const uint4* srcq = (const uint4*)g_qs + (size_t)(n*NT + tile)*2048;
    for (int i=tid; i<2048; i+=512) dst[i] = srcq[i];
  }
  stageWH(ms, g_M + (size_t)n*CH*CH, tid, CH);
  __syncthreads();

  float acc[2][4][4];
  gemm16(smem_u32(ms), smem_u32(xs), acc, wr, wc, lane);

  float* og = out + (size_t)n*CH*LEN + l0;
#pragma unroll
  for (int m=0;m<2;m++){
    const int rt = wr*32 + m*16 + lr, rb = rt + 8;
    const float bt = __ldg(br + rt), bb = __ldg(br + rb);
#pragma unroll
    for (int nn=0;nn<4;nn++){
      int c = wc*32 + nn*8 + lc*2;
      *(float2*)(og + (size_t)rt*LEN + c) = make_float2(acc[m][nn][0]+bt, acc[m][nn][1]+bt);
      *(float2*)(og + (size_t)rb*LEN + c) = make_float2(acc[m][nn][2]+bb, acc[m][nn][3]+bb);
    }
  }
}

extern "C" void kernel_launch(void* const* d_in, const int* in_sizes, int n_in,
                              void* d_out, int out_size)
{
  const float* x  = (const float*)d_in[0];
  const float* CLS= (const float*)d_in[1];
  const float* Wk = (const float*)d_in[2];
  const float* bk = (const float*)d_in[3];
  const float* Wq = (const float*)d_in[4];
  const float* bq = (const float*)d_in[5];
  const float* Wv = (const float*)d_in[6];
  const float* bv = (const float*)d_in[7];
  const float* Wr = (const float*)d_in[8];
  const float* br = (const float*)d_in[9];
  float* out = (float*)d_out;

  cudaFuncSetAttribute(proj_kernel, cudaFuncAttributeMaxDynamicSharedMemorySize, SMEM_PROJ);
  cudaFuncSetAttribute(out_kernel,  cudaFuncAttributeMaxDynamicSharedMemorySize, SMEM_OUT);

  dim3 grid(NT, NB);
  proj_kernel<<<grid, 512, SMEM_PROJ>>>(x, Wk, bk, Wq, bq, Wv, bv);
  finalize_kernel<<<NB, 512>>>(CLS, Wr, out);
  out_kernel<<<grid, 512, SMEM_OUT>>>(br, out);
}

// round 10
// speedup vs baseline: 5.2974x; 1.8120x over previous
#include <cuda_runtime.h>
#include <cuda_fp16.h>
#include <cstdint>

// EfficientAttention3D — fp16 mma.sync m16n8k16 (R10).
//   proj_kernel  : unchanged from R9 (151us).
//   reduce_kernel: NEW — tile-reduction of g_part spread over 34 CTAs (was 2).
//   finalize     : now reads the tiny reduced g_ctx; builds M, context_last, CLS_out.
//   out_kernel   : 4 tiles per CTA — M staged once per CTA.

#define NB   2
#define CH   128
#define LEN  65536
#define TL   128
#define NT   (LEN/TL)
#define NCLS 4
#define OT   4          // tiles per out CTA

// proj smem byte offsets
#define B_XS 0          // 32KB x tile [l][ch] fp16 rotated
#define B_WA 32768      // 32KB Wq -> qstage -> Wv -> vs
#define B_WB 65536      // 32KB Wk -> es
#define B_RS 98304      // 2KB rowsum partials
#define SMEM_PROJ 100352
#define SMEM_OUT  65536

__device__ __align__(16) __half g_qs[(size_t)NB*NT*16384];   // per-tile rotated [l][ch]
__device__ float g_part[(size_t)NB*2176*NT];                 // [n][elem][tile]
__device__ float g_ctx[NB*2176];                             // reduced
__device__ float g_M[NB*CH*CH];

__device__ __forceinline__ uint32_t smem_u32(const void* p){
  uint32_t a; asm("{ .reg .u64 t; cvta.to.shared.u64 t, %1; cvt.u32.u64 %0, t; }":"=r"(a):"l"(p)); return a;
}
__device__ __forceinline__ void mma16(float d[4], const uint32_t a[4], uint32_t b0, uint32_t b1){
  asm volatile("mma.sync.aligned.m16n8k16.row.col.f32.f16.f16.f32 "
    "{%0,%1,%2,%3}, {%4,%5,%6,%7}, {%8,%9}, {%0,%1,%2,%3};"
    : "+f"(d[0]),"+f"(d[1]),"+f"(d[2]),"+f"(d[3])
    : "r"(a[0]),"r"(a[1]),"r"(a[2]),"r"(a[3]),"r"(b0),"r"(b1));
}
__device__ __forceinline__ void ldsm4(uint32_t* r, uint32_t a){
  asm volatile("ldmatrix.sync.aligned.m8n8.x4.shared.b16 {%0,%1,%2,%3}, [%4];"
    : "=r"(r[0]),"=r"(r[1]),"=r"(r[2]),"=r"(r[3]) : "r"(a));
}

// rotated-chunk layout: element (r,c) of a [R][128] fp16 tile lives at
//   r*256 + (((c>>3)+r)&15)*16 + (c&7)*2
__device__ __forceinline__ void stH2(__half* b, int r, int c, float v0, float v1){
  *(__half2*)((char*)b + r*256 + ((((c>>3)+r)&15)<<4) + (c&7)*2) = __floats2half2_rn(v0,v1);
}

__device__ __forceinline__ void stageXT(__half* xs, const float* __restrict__ src, int tid, size_t srcPitch){
  const int l = tid&127, cg = tid>>7;
#pragma unroll
  for (int pass=0; pass<4; pass++){
    const int c0 = pass*32 + cg*8;
    __half h[8];
#pragma unroll
    for (int i=0;i<8;i++) h[i] = __float2half(__ldg(src + (size_t)(c0+i)*srcPitch + l));
    *(uint4*)((char*)xs + l*256 + ((((c0>>3)+l)&15)<<4)) = *(uint4*)h;
  }
}
__device__ __forceinline__ void stageWH(__half* ws, const float* __restrict__ src, int tid, int srcPitch){
  const int o = tid>>4, ch = tid&15;
#pragma unroll
  for (int pass=0; pass<4; pass++){
    const int oo = pass*32 + o;
    const float* p = src + (size_t)oo*srcPitch + ch*8;
    float4 f0 = *(const float4*)p, f1 = *(const float4*)(p+4);
    __half h[8] = {__float2half(f0.x),__float2half(f0.y),__float2half(f0.z),__float2half(f0.w),
                   __float2half(f1.x),__float2half(f1.y),__float2half(f1.z),__float2half(f1.w)};
    *(uint4*)((char*)ws + oo*256 + (((ch+oo)&15)<<4)) = *(uint4*)h;
  }
}

// A: ws [128 m][128 k] fp16 rotated; B: xs [128 n][128 k] fp16 rotated. Warp tile 32x32.
__device__ __forceinline__ void gemm16(uint32_t wsb, uint32_t xsb, float acc[2][4][4],
                                       int wr, int wc, int lane)
{
#pragma unroll
  for (int m=0;m<2;m++)
#pragma unroll
    for (int n=0;n<4;n++)
#pragma unroll
      for (int j=0;j<4;j++) acc[m][n][j]=0.f;
  const int ar0 = wr*32 + (lane&15), ar1 = ar0 + 16;
  const int ach = lane>>4;
  const uint32_t a0b = wsb + ar0*256, a1b = wsb + ar1*256;
  const int br0 = wc*32 + (lane&7) + ((lane>>4)<<3), br1 = br0 + 16;
  const int bch = (lane>>3)&1;
  const uint32_t b0b = xsb + br0*256, b1b = xsb + br1*256;
#pragma unroll
  for (int k=0;k<8;k++){
    uint32_t a0[4],a1[4],b0[4],b1[4];
    ldsm4(a0, a0b + (((2*k+ach+ar0)&15)<<4));
    ldsm4(a1, a1b + (((2*k+ach+ar1)&15)<<4));
    ldsm4(b0, b0b + (((2*k+bch+br0)&15)<<4));
    ldsm4(b1, b1b + (((2*k+bch+br1)&15)<<4));
    mma16(acc[0][0], a0, b0[0], b0[1]); mma16(acc[1][0], a1, b0[0], b0[1]);
    mma16(acc[0][1], a0, b0[2], b0[3]); mma16(acc[1][1], a1, b0[2], b0[3]);
    mma16(acc[0][2], a0, b1[0], b1[1]); mma16(acc[1][2], a1, b1[0], b1[1]);
    mma16(acc[0][3], a0, b1[2], b1[3]); mma16(acc[1][3], a1, b1[2], b1[3]);
  }
}

extern "C" __global__ void __launch_bounds__(512,1)
proj_kernel(const float* __restrict__ x,
            const float* __restrict__ Wk, const float* __restrict__ bk,
            const float* __restrict__ Wq, const float* __restrict__ bq,
            const float* __restrict__ Wv, const float* __restrict__ bv)
{
  extern __shared__ char smb[];
  __half* xs = (__half*)(smb + B_XS);
  __half* wA = (__half*)(smb + B_WA);
  __half* wB = (__half*)(smb + B_WB);
  float*  rs = (float*)(smb + B_RS);
  const int tid = threadIdx.x, wid = tid>>5, lane = tid&31;
  const int wr = wid&3, wc = wid>>2, lr = lane>>2, lc = lane&3;
  const int n = blockIdx.y, tile = blockIdx.x, l0 = tile*TL;
  const uint32_t xsb = smem_u32(xs), wAb = smem_u32(wA), wBb = smem_u32(wB);

  stageXT(xs, x + (size_t)n*CH*LEN + l0, tid, LEN);
  stageWH(wA, Wq, tid, CH);
  stageWH(wB, Wk, tid, CH);
  __syncthreads();

  float accQ[2][4][4], accK[2][4][4];
  gemm16(wAb, xsb, accQ, wr, wc, lane);
  gemm16(wBb, xsb, accK, wr, wc, lane);
  __syncthreads();

  // ---- Q epilogue: exp + 16-channel softmax -> wA as [l][ch] fp16 rotated ----
  {
    __half* qh = wA;
#pragma unroll
    for (int m=0;m<2;m++){
      const int rt = wr*32 + m*16 + lr, rb = rt + 8;
      const float bt = __ldg(bq + rt), bb = __ldg(bq + rb);
      float e[4][4], s0[4], s1[4];
#pragma unroll
      for (int nn=0;nn<4;nn++){
        e[nn][0]=__expf(accQ[m][nn][0]+bt); e[nn][1]=__expf(accQ[m][nn][1]+bt);
        e[nn][2]=__expf(accQ[m][nn][2]+bb); e[nn][3]=__expf(accQ[m][nn][3]+bb);
        s0[nn]=e[nn][0]+e[nn][2]; s1[nn]=e[nn][1]+e[nn][3];
      }
#pragma unroll
      for (int nn=0;nn<4;nn++){
        s0[nn] += __shfl_xor_sync(0xffffffffu, s0[nn], 4);
        s0[nn] += __shfl_xor_sync(0xffffffffu, s0[nn], 8);
        s0[nn] += __shfl_xor_sync(0xffffffffu, s0[nn], 16);
        s1[nn] += __shfl_xor_sync(0xffffffffu, s1[nn], 4);
        s1[nn] += __shfl_xor_sync(0xffffffffu, s1[nn], 8);
        s1[nn] += __shfl_xor_sync(0xffffffffu, s1[nn], 16);
        float i0 = __frcp_rn(s0[nn]), i1 = __frcp_rn(s1[nn]);
        int c = wc*32 + nn*8 + lc*2;
        *(__half*)((char*)qh + c*256     + ((((rt>>3)+c  )&15)<<4) + (rt&7)*2) = __float2half(e[nn][0]*i0);
        *(__half*)((char*)qh + (c+1)*256 + ((((rt>>3)+c+1)&15)<<4) + (rt&7)*2) = __float2half(e[nn][1]*i1);
        *(__half*)((char*)qh + c*256     + ((((rb>>3)+c  )&15)<<4) + (rb&7)*2) = __float2half(e[nn][2]*i0);
        *(__half*)((char*)qh + (c+1)*256 + ((((rb>>3)+c+1)&15)<<4) + (rb&7)*2) = __float2half(e[nn][3]*i1);
      }
    }
  }
  // ---- K epilogue: exp -> wB = es (+ rowsums) ----
#pragma unroll
  for (int m=0;m<2;m++){
    const int rt = wr*32 + m*16 + lr, rb = rt + 8;
    const float bt = __ldg(bk + rt), bb = __ldg(bk + rb);
    float rowt=0.f, rowb=0.f;
#pragma unroll
    for (int nn=0;nn<4;nn++){
      float e0=__expf(accK[m][nn][0]+bt), e1=__expf(accK[m][nn][1]+bt);
      float e2=__expf(accK[m][nn][2]+bb), e3=__expf(accK[m][nn][3]+bb);
      rowt += e0+e1; rowb += e2+e3;
      int c = wc*32 + nn*8 + lc*2;
      stH2(wB, rt, c, e0, e1);
      stH2(wB, rb, c, e2, e3);
    }
    rowt += __shfl_xor_sync(0xffffffffu, rowt, 1);
    rowt += __shfl_xor_sync(0xffffffffu, rowt, 2);
    rowb += __shfl_xor_sync(0xffffffffu, rowb, 1);
    rowb += __shfl_xor_sync(0xffffffffu, rowb, 2);
    if (lc == 0){ rs[rt*4+wc]=rowt; rs[rb*4+wc]=rowb; }
  }
  __syncthreads();

  // ---- copy qstage -> g_qs ----
  {
    uint4* dst = (uint4*)g_qs + (size_t)(n*NT + tile)*2048;
    const uint4* srcq = (const uint4*)wA;
    for (int i=tid; i<2048; i+=512) dst[i] = srcq[i];
  }
  __syncthreads();
  stageWH(wA, Wv, tid, CH);
  __syncthreads();

  // ---- V GEMM -> vs ----
  gemm16(wAb, xsb, accQ, wr, wc, lane);
  __syncthreads();
#pragma unroll
  for (int m=0;m<2;m++){
    const int rt = wr*32 + m*16 + lr, rb = rt + 8;
    const float bt = __ldg(bv + rt), bb = __ldg(bv + rb);
#pragma unroll
    for (int nn=0;nn<4;nn++){
      int c = wc*32 + nn*8 + lc*2;
      stH2(wA, rt, c, accQ[m][nn][0]+bt, accQ[m][nn][1]+bt);
      stH2(wA, rb, c, accQ[m][nn][2]+bb, accQ[m][nn][3]+bb);
    }
  }
  __syncthreads();

  // ---- context: ctx[h] = E_h @ V_h^T ----
  float* pb = g_part + (size_t)n*2176*NT + tile;
  float* cbuf = (float*)xs;
  {
    const int h = wid>>1, kh = wid&1;
    const int ar = h*16 + (lane&15);
    const int ach = (lane>>4);
    const int brr = h*16 + (lane&7) + ((lane>>4)<<3);
    const int bch = (lane>>3)&1;
    const uint32_t ab = wBb + ar*256;
    const uint32_t bbv = wAb + brr*256;
    float ca[2][4];
#pragma unroll
    for (int nt=0;nt<2;nt++)
#pragma unroll
      for (int j=0;j<4;j++) ca[nt][j]=0.f;
#pragma unroll
    for (int ks=0;ks<4;ks++){
      const int c2 = kh*8 + ks*2;
      uint32_t a[4], b[4];
      ldsm4(a, ab  + (((c2+ach+ar )&15)<<4));
      ldsm4(b, bbv + (((c2+bch+brr)&15)<<4));
      mma16(ca[0], a, b[0], b[1]);
      mma16(ca[1], a, b[2], b[3]);
    }
    if (kh == 1){
#pragma unroll
      for (int nt=0;nt<2;nt++){
        int v = nt*8 + lc*2;
        *(float2*)(cbuf + h*256 + lr*16     + v) = make_float2(ca[nt][0], ca[nt][1]);
        *(float2*)(cbuf + h*256 + (lr+8)*16 + v) = make_float2(ca[nt][2], ca[nt][3]);
      }
    }
    __syncthreads();
    if (kh == 0){
#pragma unroll
      for (int nt=0;nt<2;nt++){
        int v = nt*8 + lc*2;
        pb[(size_t)(h*256 + lr*16 + v    )*NT] = ca[nt][0] + cbuf[h*256 + lr*16 + v];
        pb[(size_t)(h*256 + lr*16 + v + 1)*NT] = ca[nt][1] + cbuf[h*256 + lr*16 + v + 1];
        pb[(size_t)(h*256 + (lr+8)*16 + v    )*NT] = ca[nt][2] + cbuf[h*256 + (lr+8)*16 + v];
        pb[(size_t)(h*256 + (lr+8)*16 + v + 1)*NT] = ca[nt][3] + cbuf[h*256 + (lr+8)*16 + v + 1];
      }
    }
  }
  if (tid < CH)
    pb[(size_t)(2048 + tid)*NT] = rs[tid*4] + rs[tid*4+1] + rs[tid*4+2] + rs[tid*4+3];
}

// ---------------- reduce: g_part [elem][NT] -> g_ctx [elem], many CTAs ----------------
extern "C" __global__ void __launch_bounds__(512,1)
reduce_kernel()
{
  const int n = blockIdx.y;
  const int tid = threadIdx.x, wid = tid>>5, lane = tid&31;
  const int o0 = (blockIdx.x*16 + wid)*8;     // 17 CTAs x 16 warps x 8 elems = 2176
#pragma unroll
  for (int j=0;j<8;j++){
    const int o = o0 + j;
    const float* p = g_part + ((size_t)n*2176 + o)*NT + lane*4;
    float s = 0.f;
#pragma unroll
    for (int i=0;i<4;i++){ float4 v = *(const float4*)(p + i*128); s += v.x+v.y+v.z+v.w; }
    s += __shfl_xor_sync(0xffffffffu, s, 16);
    s += __shfl_xor_sync(0xffffffffu, s, 8);
    s += __shfl_xor_sync(0xffffffffu, s, 4);
    s += __shfl_xor_sync(0xffffffffu, s, 2);
    s += __shfl_xor_sync(0xffffffffu, s, 1);
    if (lane == 0) g_ctx[n*2176 + o] = s;
  }
}

// ---------------- finalize (tiny now) ----------------
extern "C" __global__ void __launch_bounds__(512,1)
finalize_kernel(const float* __restrict__ CLS,
                const float* __restrict__ Wr,
                float* __restrict__ out)
{
  __shared__ float ctx[2048];
  __shared__ float Ssum[128];
  __shared__ float ecls[512];
  __shared__ float clsv[512];
  __shared__ float cn[2048];
  const int n = blockIdx.x;
  const int tid = threadIdx.x;

  for (int o=tid; o<2176; o+=512){
    float s = g_ctx[n*2176 + o];
    if (o < 2048) ctx[o] = s; else Ssum[o-2048] = s;
  }
  if (tid < 512){
    float v = CLS[(size_t)n*CH*NCLS + tid];
    clsv[tid]=v; ecls[tid]=__expf(v);
  }
  __syncthreads();
  if (tid < 128){
    float s = Ssum[tid];
#pragma unroll
    for (int j=0;j<NCLS;j++) s += ecls[tid*NCLS+j];
    Ssum[tid]=s;
  }
  __syncthreads();
  for (int idx=tid; idx<2048; idx+=512){
    int h=idx>>8, k=(idx>>4)&15, v=idx&15;
    float s=ctx[idx];
#pragma unroll
    for (int j=0;j<NCLS;j++) s += ecls[(h*16+k)*NCLS+j]*clsv[(h*16+v)*NCLS+j];
    cn[idx] = s / Ssum[h*16+k];
  }
  __syncthreads();
  if (tid < 256) out[(size_t)NB*CH*LEN + n*256 + tid] = cn[7*256 + tid];
  if (tid < 64){
    int v=tid>>2, j=tid&3;
    float se=0.f, a=0.f;
#pragma unroll
    for (int k=0;k<16;k++){
      float e = ecls[(112+k)*NCLS + j];
      se += e;
      a  += cn[7*256 + k*16 + v]*e;
    }
    out[(size_t)NB*CH*LEN + (size_t)NB*256 + n*64 + v*4 + j] = a/se;
  }
  for (int idx=tid; idx<CH*CH; idx+=512){
    int o=idx>>7, c=idx&127, h=c>>4, k=c&15;
    float m=0.f;
#pragma unroll
    for (int v=0;v<16;v++) m += Wr[o*CH + h*16+v]*cn[h*256 + k*16 + v];
    g_M[(size_t)n*CH*CH + idx] = m;
  }
}

// ---------------- out: attention = M @ qs + br, OT tiles per CTA ----------------
extern "C" __global__ void __launch_bounds__(512,1)
out_kernel(const float* __restrict__ br, float* __restrict__ out)
{
  extern __shared__ char smb[];
  __half* xs = (__half*)smb;            // qs tile (raw copy)
  __half* ms = (__half*)(smb + 32768);  // M fp16 rotated (staged once)
  const int tid = threadIdx.x, wid = tid>>5, lane = tid&31;
  const int wr = wid&3, wc = wid>>2, lr = lane>>2, lc = lane&3;
  const int n = blockIdx.y;
  const uint32_t msb = smem_u32(ms), xsb = smem_u32(xs);

  stageWH(ms, g_M + (size_t)n*CH*CH, tid, CH);

  const float bt0[2] = { __ldg(br + wr*32 + lr), __ldg(br + wr*32 + 16 + lr) };
  const float bb0[2] = { __ldg(br + wr*32 + 8 + lr), __ldg(br + wr*32 + 24 + lr) };

  for (int t=0; t<OT; t++){
    const int tile = blockIdx.x*OT + t;
    __syncthreads();   // previous gemm's xs reads done (and ms staged on t=0)
    {
      uint4* dst = (uint4*)xs;
      const uint4* srcq = (const uint4*)g_qs + (size_t)(n*NT + tile)*2048;
      for (int i=tid; i<2048; i+=512) dst[i] = srcq[i];
    }
    __syncthreads();

    float acc[2][4][4];
    gemm16(msb, xsb, acc, wr, wc, lane);

    float* og = out + (size_t)n*CH*LEN + tile*TL;
#pragma unroll
    for (int m=0;m<2;m++){
      const int rt = wr*32 + m*16 + lr, rb = rt + 8;
#pragma unroll
      for (int nn=0;nn<4;nn++){
        int c = wc*32 + nn*8 + lc*2;
        *(float2*)(og + (size_t)rt*LEN + c) = make_float2(acc[m][nn][0]+bt0[m], acc[m][nn][1]+bt0[m]);
        *(float2*)(og + (size_t)rb*LEN + c) = make_float2(acc[m][nn][2]+bb0[m], acc[m][nn][3]+bb0[m]);
      }
    }
  }
}

extern "C" void kernel_launch(void* const* d_in, const int* in_sizes, int n_in,
                              void* d_out, int out_size)
{
  const float* x  = (const float*)d_in[0];
  const float* CLS= (const float*)d_in[1];
  const float* Wk = (const float*)d_in[2];
  const float* bk = (const float*)d_in[3];
  const float* Wq = (const float*)d_in[4];
  const float* bq = (const float*)d_in[5];
  const float* Wv = (const float*)d_in[6];
  const float* bv = (const float*)d_in[7];
  const float* Wr = (const float*)d_in[8];
  const float* br = (const float*)d_in[9];
  float* out = (float*)d_out;

  cudaFuncSetAttribute(proj_kernel, cudaFuncAttributeMaxDynamicSharedMemorySize, SMEM_PROJ);
  cudaFuncSetAttribute(out_kernel,  cudaFuncAttributeMaxDynamicSharedMemorySize, SMEM_OUT);

  dim3 gp(NT, NB);
  proj_kernel<<<gp, 512, SMEM_PROJ>>>(x, Wk, bk, Wq, bq, Wv, bv);
  dim3 gr(17, NB);
  reduce_kernel<<<gr, 512>>>();
  finalize_kernel<<<NB, 512>>>(CLS, Wr, out);
  dim3 go(NT/OT, NB);
  out_kernel<<<go, 512, SMEM_OUT>>>(br, out);
}

// round 11
// speedup vs baseline: 5.9507x; 1.1233x over previous
#include <cuda_runtime.h>
#include <cuda_fp16.h>
#include <cstdint>

// EfficientAttention3D — fp16 mma.sync m16n8k16 (R11).
//   proj_kernel  : R10 + dedicated qbuf; g_qs copy overlapped with V GEMM,
//                  Wv staging LDGs issued before exp epilogues. 2 fewer syncs.
//   reduce_kernel: unchanged (34-CTA tile reduction).
//   finalize     : unchanged.
//   out_kernel   : OT=8 (single wave, 128 CTAs), double-buffered qs tiles with
//                  register prefetch under the GEMM, streaming stores.

#define NB   2
#define CH   128
#define LEN  65536
#define TL   128
#define NT   (LEN/TL)
#define NCLS 4
#define OT   8          // tiles per out CTA

// proj smem byte offsets
#define B_XS 0          // 32KB x tile [l][ch] fp16 rotated
#define B_WA 32768      // 32KB Wq -> Wv -> vs
#define B_WB 65536      // 32KB Wk -> es
#define B_QB 98304      // 32KB q staging (rotated [l][ch])
#define B_RS 131072     // 2KB rowsum partials
#define SMEM_PROJ 133120
// out smem
#define SMEM_OUT  98304  // xs0 32KB, xs1 32KB, ms 32KB

__device__ __align__(16) __half g_qs[(size_t)NB*NT*16384];   // per-tile rotated [l][ch]
__device__ float g_part[(size_t)NB*2176*NT];                 // [n][elem][tile]
__device__ float g_ctx[NB*2176];
__device__ float g_M[NB*CH*CH];

__device__ __forceinline__ uint32_t smem_u32(const void* p){
  uint32_t a; asm("{ .reg .u64 t; cvta.to.shared.u64 t, %1; cvt.u32.u64 %0, t; }":"=r"(a):"l"(p)); return a;
}
__device__ __forceinline__ void mma16(float d[4], const uint32_t a[4], uint32_t b0, uint32_t b1){
  asm volatile("mma.sync.aligned.m16n8k16.row.col.f32.f16.f16.f32 "
    "{%0,%1,%2,%3}, {%4,%5,%6,%7}, {%8,%9}, {%0,%1,%2,%3};"
    : "+f"(d[0]),"+f"(d[1]),"+f"(d[2]),"+f"(d[3])
    : "r"(a[0]),"r"(a[1]),"r"(a[2]),"r"(a[3]),"r"(b0),"r"(b1));
}
__device__ __forceinline__ void ldsm4(uint32_t* r, uint32_t a){
  asm volatile("ldmatrix.sync.aligned.m8n8.x4.shared.b16 {%0,%1,%2,%3}, [%4];"
    : "=r"(r[0]),"=r"(r[1]),"=r"(r[2]),"=r"(r[3]) : "r"(a));
}

// rotated-chunk layout: element (r,c) of a [R][128] fp16 tile lives at
//   r*256 + (((c>>3)+r)&15)*16 + (c&7)*2
__device__ __forceinline__ void stH2(__half* b, int r, int c, float v0, float v1){
  *(__half2*)((char*)b + r*256 + ((((c>>3)+r)&15)<<4) + (c&7)*2) = __floats2half2_rn(v0,v1);
}

__device__ __forceinline__ void stageXT(__half* xs, const float* __restrict__ src, int tid, size_t srcPitch){
  const int l = tid&127, cg = tid>>7;
#pragma unroll
  for (int pass=0; pass<4; pass++){
    const int c0 = pass*32 + cg*8;
    __half h[8];
#pragma unroll
    for (int i=0;i<8;i++) h[i] = __float2half(__ldg(src + (size_t)(c0+i)*srcPitch + l));
    *(uint4*)((char*)xs + l*256 + ((((c0>>3)+l)&15)<<4)) = *(uint4*)h;
  }
}
__device__ __forceinline__ void stageWH(__half* ws, const float* __restrict__ src, int tid, int srcPitch){
  const int o = tid>>4, ch = tid&15;
#pragma unroll
  for (int pass=0; pass<4; pass++){
    const int oo = pass*32 + o;
    const float* p = src + (size_t)oo*srcPitch + ch*8;
    float4 f0 = *(const float4*)p, f1 = *(const float4*)(p+4);
    __half h[8] = {__float2half(f0.x),__float2half(f0.y),__float2half(f0.z),__float2half(f0.w),
                   __float2half(f1.x),__float2half(f1.y),__float2half(f1.z),__float2half(f1.w)};
    *(uint4*)((char*)ws + oo*256 + (((ch+oo)&15)<<4)) = *(uint4*)h;
  }
}

// A: ws [128 m][128 k] fp16 rotated; B: xs [128 n][128 k] fp16 rotated. Warp tile 32x32.
__device__ __forceinline__ void gemm16(uint32_t wsb, uint32_t xsb, float acc[2][4][4],
                                       int wr, int wc, int lane)
{
#pragma unroll
  for (int m=0;m<2;m++)
#pragma unroll
    for (int n=0;n<4;n++)
#pragma unroll
      for (int j=0;j<4;j++) acc[m][n][j]=0.f;
  const int ar0 = wr*32 + (lane&15), ar1 = ar0 + 16;
  const int ach = lane>>4;
  const uint32_t a0b = wsb + ar0*256, a1b = wsb + ar1*256;
  const int br0 = wc*32 + (lane&7) + ((lane>>4)<<3), br1 = br0 + 16;
  const int bch = (lane>>3)&1;
  const uint32_t b0b = xsb + br0*256, b1b = xsb + br1*256;
#pragma unroll
  for (int k=0;k<8;k++){
    uint32_t a0[4],a1[4],b0[4],b1[4];
    ldsm4(a0, a0b + (((2*k+ach+ar0)&15)<<4));
    ldsm4(a1, a1b + (((2*k+ach+ar1)&15)<<4));
    ldsm4(b0, b0b + (((2*k+bch+br0)&15)<<4));
    ldsm4(b1, b1b + (((2*k+bch+br1)&15)<<4));
    mma16(acc[0][0], a0, b0[0], b0[1]); mma16(acc[1][0], a1, b0[0], b0[1]);
    mma16(acc[0][1], a0, b0[2], b0[3]); mma16(acc[1][1], a1, b0[2], b0[3]);
    mma16(acc[0][2], a0, b1[0], b1[1]); mma16(acc[1][2], a1, b1[0], b1[1]);
    mma16(acc[0][3], a0, b1[2], b1[3]); mma16(acc[1][3], a1, b1[2], b1[3]);
  }
}

extern "C" __global__ void __launch_bounds__(512,1)
proj_kernel(const float* __restrict__ x,
            const float* __restrict__ Wk, const float* __restrict__ bk,
            const float* __restrict__ Wq, const float* __restrict__ bq,
            const float* __restrict__ Wv, const float* __restrict__ bv)
{
  extern __shared__ char smb[];
  __half* xs = (__half*)(smb + B_XS);
  __half* wA = (__half*)(smb + B_WA);
  __half* wB = (__half*)(smb + B_WB);
  __half* qb = (__half*)(smb + B_QB);
  float*  rs = (float*)(smb + B_RS);
  const int tid = threadIdx.x, wid = tid>>5, lane = tid&31;
  const int wr = wid&3, wc = wid>>2, lr = lane>>2, lc = lane&3;
  const int n = blockIdx.y, tile = blockIdx.x, l0 = tile*TL;
  const uint32_t xsb = smem_u32(xs), wAb = smem_u32(wA), wBb = smem_u32(wB);

  stageXT(xs, x + (size_t)n*CH*LEN + l0, tid, LEN);
  stageWH(wA, Wq, tid, CH);
  stageWH(wB, Wk, tid, CH);
  __syncthreads();

  float accQ[2][4][4], accK[2][4][4];
  gemm16(wAb, xsb, accQ, wr, wc, lane);
  gemm16(wBb, xsb, accK, wr, wc, lane);
  __syncthreads();   // wA(Wq), wB(Wk) reads done

  // stage Wv early (LDG latency hides under exp epilogues)
  stageWH(wA, Wv, tid, CH);

  // ---- Q epilogue: exp + 16-channel softmax -> qb as [l][ch] fp16 rotated ----
#pragma unroll
  for (int m=0;m<2;m++){
    const int rt = wr*32 + m*16 + lr, rb = rt + 8;
    const float bt = __ldg(bq + rt), bb = __ldg(bq + rb);
    float e[4][4], s0[4], s1[4];
#pragma unroll
    for (int nn=0;nn<4;nn++){
      e[nn][0]=__expf(accQ[m][nn][0]+bt); e[nn][1]=__expf(accQ[m][nn][1]+bt);
      e[nn][2]=__expf(accQ[m][nn][2]+bb); e[nn][3]=__expf(accQ[m][nn][3]+bb);
      s0[nn]=e[nn][0]+e[nn][2]; s1[nn]=e[nn][1]+e[nn][3];
    }
#pragma unroll
    for (int nn=0;nn<4;nn++){
      s0[nn] += __shfl_xor_sync(0xffffffffu, s0[nn], 4);
      s0[nn] += __shfl_xor_sync(0xffffffffu, s0[nn], 8);
      s0[nn] += __shfl_xor_sync(0xffffffffu, s0[nn], 16);
      s1[nn] += __shfl_xor_sync(0xffffffffu, s1[nn], 4);
      s1[nn] += __shfl_xor_sync(0xffffffffu, s1[nn], 8);
      s1[nn] += __shfl_xor_sync(0xffffffffu, s1[nn], 16);
      float i0 = __frcp_rn(s0[nn]), i1 = __frcp_rn(s1[nn]);
      int c = wc*32 + nn*8 + lc*2;
      *(__half*)((char*)qb + c*256     + ((((rt>>3)+c  )&15)<<4) + (rt&7)*2) = __float2half(e[nn][0]*i0);
      *(__half*)((char*)qb + (c+1)*256 + ((((rt>>3)+c+1)&15)<<4) + (rt&7)*2) = __float2half(e[nn][1]*i1);
      *(__half*)((char*)qb + c*256     + ((((rb>>3)+c  )&15)<<4) + (rb&7)*2) = __float2half(e[nn][2]*i0);
      *(__half*)((char*)qb + (c+1)*256 + ((((rb>>3)+c+1)&15)<<4) + (rb&7)*2) = __float2half(e[nn][3]*i1);
    }
  }
  // ---- K epilogue: exp -> wB = es (+ rowsums) ----
#pragma unroll
  for (int m=0;m<2;m++){
    const int rt = wr*32 + m*16 + lr, rb = rt + 8;
    const float bt = __ldg(bk + rt), bb = __ldg(bk + rb);
    float rowt=0.f, rowb=0.f;
#pragma unroll
    for (int nn=0;nn<4;nn++){
      float e0=__expf(accK[m][nn][0]+bt), e1=__expf(accK[m][nn][1]+bt);
      float e2=__expf(accK[m][nn][2]+bb), e3=__expf(accK[m][nn][3]+bb);
      rowt += e0+e1; rowb += e2+e3;
      int c = wc*32 + nn*8 + lc*2;
      stH2(wB, rt, c, e0, e1);
      stH2(wB, rb, c, e2, e3);
    }
    rowt += __shfl_xor_sync(0xffffffffu, rowt, 1);
    rowt += __shfl_xor_sync(0xffffffffu, rowt, 2);
    rowb += __shfl_xor_sync(0xffffffffu, rowb, 1);
    rowb += __shfl_xor_sync(0xffffffffu, rowb, 2);
    if (lc == 0){ rs[rt*4+wc]=rowt; rs[rb*4+wc]=rowb; }
  }
  __syncthreads();   // qb/es written, Wv staged

  // ---- V GEMM; qs copy overlaps (independent of wA/xs) ----
  gemm16(wAb, xsb, accQ, wr, wc, lane);
  {
    uint4* dst = (uint4*)g_qs + (size_t)(n*NT + tile)*2048;
    const uint4* srcq = (const uint4*)qb;
    for (int i=tid; i<2048; i+=512) dst[i] = srcq[i];
  }
  __syncthreads();   // wA(Wv) reads + qb reads done
#pragma unroll
  for (int m=0;m<2;m++){
    const int rt = wr*32 + m*16 + lr, rb = rt + 8;
    const float bt = __ldg(bv + rt), bb = __ldg(bv + rb);
#pragma unroll
    for (int nn=0;nn<4;nn++){
      int c = wc*32 + nn*8 + lc*2;
      stH2(wA, rt, c, accQ[m][nn][0]+bt, accQ[m][nn][1]+bt);
      stH2(wA, rb, c, accQ[m][nn][2]+bb, accQ[m][nn][3]+bb);
    }
  }
  __syncthreads();

  // ---- context: ctx[h] = E_h @ V_h^T ----
  float* pb = g_part + (size_t)n*2176*NT + tile;
  float* cbuf = (float*)xs;
  {
    const int h = wid>>1, kh = wid&1;
    const int ar = h*16 + (lane&15);
    const int ach = (lane>>4);
    const int brr = h*16 + (lane&7) + ((lane>>4)<<3);
    const int bch = (lane>>3)&1;
    const uint32_t ab = wBb + ar*256;
    const uint32_t bbv = wAb + brr*256;
    float ca[2][4];
#pragma unroll
    for (int nt=0;nt<2;nt++)
#pragma unroll
      for (int j=0;j<4;j++) ca[nt][j]=0.f;
#pragma unroll
    for (int ks=0;ks<4;ks++){
      const int c2 = kh*8 + ks*2;
      uint32_t a[4], b[4];
      ldsm4(a, ab  + (((c2+ach+ar )&15)<<4));
      ldsm4(b, bbv + (((c2+bch+brr)&15)<<4));
      mma16(ca[0], a, b[0], b[1]);
      mma16(ca[1], a, b[2], b[3]);
    }
    if (kh == 1){
#pragma unroll
      for (int nt=0;nt<2;nt++){
        int v = nt*8 + lc*2;
        *(float2*)(cbuf + h*256 + lr*16     + v) = make_float2(ca[nt][0], ca[nt][1]);
        *(float2*)(cbuf + h*256 + (lr+8)*16 + v) = make_float2(ca[nt][2], ca[nt][3]);
      }
    }
    __syncthreads();
    if (kh == 0){
#pragma unroll
      for (int nt=0;nt<2;nt++){
        int v = nt*8 + lc*2;
        pb[(size_t)(h*256 + lr*16 + v    )*NT] = ca[nt][0] + cbuf[h*256 + lr*16 + v];
        pb[(size_t)(h*256 + lr*16 + v + 1)*NT] = ca[nt][1] + cbuf[h*256 + lr*16 + v + 1];
        pb[(size_t)(h*256 + (lr+8)*16 + v    )*NT] = ca[nt][2] + cbuf[h*256 + (lr+8)*16 + v];
        pb[(size_t)(h*256 + (lr+8)*16 + v + 1)*NT] = ca[nt][3] + cbuf[h*256 + (lr+8)*16 + v + 1];
      }
    }
  }
  if (tid < CH)
    pb[(size_t)(2048 + tid)*NT] = rs[tid*4] + rs[tid*4+1] + rs[tid*4+2] + rs[tid*4+3];
}

// ---------------- reduce: g_part [elem][NT] -> g_ctx [elem] ----------------
extern "C" __global__ void __launch_bounds__(512,1)
reduce_kernel()
{
  const int n = blockIdx.y;
  const int tid = threadIdx.x, wid = tid>>5, lane = tid&31;
  const int o0 = (blockIdx.x*16 + wid)*8;
#pragma unroll
  for (int j=0;j<8;j++){
    const int o = o0 + j;
    const float* p = g_part + ((size_t)n*2176 + o)*NT + lane*4;
    float s = 0.f;
#pragma unroll
    for (int i=0;i<4;i++){ float4 v = *(const float4*)(p + i*128); s += v.x+v.y+v.z+v.w; }
    s += __shfl_xor_sync(0xffffffffu, s, 16);
    s += __shfl_xor_sync(0xffffffffu, s, 8);
    s += __shfl_xor_sync(0xffffffffu, s, 4);
    s += __shfl_xor_sync(0xffffffffu, s, 2);
    s += __shfl_xor_sync(0xffffffffu, s, 1);
    if (lane == 0) g_ctx[n*2176 + o] = s;
  }
}

// ---------------- finalize ----------------
extern "C" __global__ void __launch_bounds__(512,1)
finalize_kernel(const float* __restrict__ CLS,
                const float* __restrict__ Wr,
                float* __restrict__ out)
{
  __shared__ float ctx[2048];
  __shared__ float Ssum[128];
  __shared__ float ecls[512];
  __shared__ float clsv[512];
  __shared__ float cn[2048];
  const int n = blockIdx.x;
  const int tid = threadIdx.x;

  for (int o=tid; o<2176; o+=512){
    float s = g_ctx[n*2176 + o];
    if (o < 2048) ctx[o] = s; else Ssum[o-2048] = s;
  }
  if (tid < 512){
    float v = CLS[(size_t)n*CH*NCLS + tid];
    clsv[tid]=v; ecls[tid]=__expf(v);
  }
  __syncthreads();
  if (tid < 128){
    float s = Ssum[tid];
#pragma unroll
    for (int j=0;j<NCLS;j++) s += ecls[tid*NCLS+j];
    Ssum[tid]=s;
  }
  __syncthreads();
  for (int idx=tid; idx<2048; idx+=512){
    int h=idx>>8, k=(idx>>4)&15, v=idx&15;
    float s=ctx[idx];
#pragma unroll
    for (int j=0;j<NCLS;j++) s += ecls[(h*16+k)*NCLS+j]*clsv[(h*16+v)*NCLS+j];
    cn[idx] = s / Ssum[h*16+k];
  }
  __syncthreads();
  if (tid < 256) out[(size_t)NB*CH*LEN + n*256 + tid] = cn[7*256 + tid];
  if (tid < 64){
    int v=tid>>2, j=tid&3;
    float se=0.f, a=0.f;
#pragma unroll
    for (int k=0;k<16;k++){
      float e = ecls[(112+k)*NCLS + j];
      se += e;
      a  += cn[7*256 + k*16 + v]*e;
    }
    out[(size_t)NB*CH*LEN + (size_t)NB*256 + n*64 + v*4 + j] = a/se;
  }
  for (int idx=tid; idx<CH*CH; idx+=512){
    int o=idx>>7, c=idx&127, h=c>>4, k=c&15;
    float m=0.f;
#pragma unroll
    for (int v=0;v<16;v++) m += Wr[o*CH + h*16+v]*cn[h*256 + k*16 + v];
    g_M[(size_t)n*CH*CH + idx] = m;
  }
}

// ---------------- out: attention = M @ qs + br, OT tiles, double-buffered ----------------
extern "C" __global__ void __launch_bounds__(512,1)
out_kernel(const float* __restrict__ br, float* __restrict__ out)
{
  extern __shared__ char smb[];
  __half* xsA[2] = { (__half*)smb, (__half*)(smb + 32768) };
  __half* ms = (__half*)(smb + 65536);
  const int tid = threadIdx.x, wid = tid>>5, lane = tid&31;
  const int wr = wid&3, wc = wid>>2, lr = lane>>2, lc = lane&3;
  const int n = blockIdx.y;
  const uint32_t msb = smem_u32(ms);
  const uint32_t xsb[2] = { smem_u32(xsA[0]), smem_u32(xsA[1]) };

  stageWH(ms, g_M + (size_t)n*CH*CH, tid, CH);

  const float bt0[2] = { __ldg(br + wr*32 + lr), __ldg(br + wr*32 + 16 + lr) };
  const float bb0[2] = { __ldg(br + wr*32 + 8 + lr), __ldg(br + wr*32 + 24 + lr) };

  const uint4* qbase = (const uint4*)g_qs + (size_t)(n*NT + blockIdx.x*OT)*2048;

  // stage tile 0
  {
    uint4* dst = (uint4*)xsA[0];
#pragma unroll
    for (int j=0;j<4;j++) dst[tid + j*512] = qbase[tid + j*512];
  }
  __syncthreads();

  int buf = 0;
  for (int t=0; t<OT; t++){
    uint4 pf[4];
    if (t+1 < OT){
      const uint4* srcq = qbase + (size_t)(t+1)*2048;
#pragma unroll
      for (int j=0;j<4;j++) pf[j] = srcq[tid + j*512];
    }

    float acc[2][4][4];
    gemm16(msb, xsb[buf], acc, wr, wc, lane);

    float* og = out + (size_t)n*CH*LEN + (blockIdx.x*OT + t)*TL;
#pragma unroll
    for (int m=0;m<2;m++){
      const int rt = wr*32 + m*16 + lr, rb = rt + 8;
#pragma unroll
      for (int nn=0;nn<4;nn++){
        int c = wc*32 + nn*8 + lc*2;
        __stcs((float2*)(og + (size_t)rt*LEN + c), make_float2(acc[m][nn][0]+bt0[m], acc[m][nn][1]+bt0[m]));
        __stcs((float2*)(og + (size_t)rb*LEN + c), make_float2(acc[m][nn][2]+bb0[m], acc[m][nn][3]+bb0[m]));
      }
    }

    if (t+1 < OT){
      uint4* dst = (uint4*)xsA[buf^1];
#pragma unroll
      for (int j=0;j<4;j++) dst[tid + j*512] = pf[j];
      __syncthreads();
      buf ^= 1;
    }
  }
}

extern "C" void kernel_launch(void* const* d_in, const int* in_sizes, int n_in,
                              void* d_out, int out_size)
{
  const float* x  = (const float*)d_in[0];
  const float* CLS= (const float*)d_in[1];
  const float* Wk = (const float*)d_in[2];
  const float* bk = (const float*)d_in[3];
  const float* Wq = (const float*)d_in[4];
  const float* bq = (const float*)d_in[5];
  const float* Wv = (const float*)d_in[6];
  const float* bv = (const float*)d_in[7];
  const float* Wr = (const float*)d_in[8];
  const float* br = (const float*)d_in[9];
  float* out = (float*)d_out;

  cudaFuncSetAttribute(proj_kernel, cudaFuncAttributeMaxDynamicSharedMemorySize, SMEM_PROJ);
  cudaFuncSetAttribute(out_kernel,  cudaFuncAttributeMaxDynamicSharedMemorySize, SMEM_OUT);

  dim3 gp(NT, NB);
  proj_kernel<<<gp, 512, SMEM_PROJ>>>(x, Wk, bk, Wq, bq, Wv, bv);
  dim3 gr(17, NB);
  reduce_kernel<<<gr, 512>>>();
  finalize_kernel<<<NB, 512>>>(CLS, Wr, out);
  dim3 go(NT/OT, NB);
  out_kernel<<<go, 512, SMEM_OUT>>>(br, out);
}